// round 4
// baseline (speedup 1.0000x reference)
#include <cuda_runtime.h>
#include <cuda_bf16.h>
#include <cstdint>
#include <cstddef>

// ============================================================================
// Windowed self-attention via mma.sync.m16n8k16 bf16 (3-term split, fp32 acc).
// ptxas target is sm_103 (no 'a') -> no tcgen05; HMMA path instead.
// Per 128-token window: q=xWq^T+bq, k=xWk^T+bk, vT=Wv x^T (+bv rows),
// S=qk^T, P=softmax(S), O=P vT^T.
// ============================================================================

#define WIN 128
#define XBUF 0
#define WBUF 65536
#define BUF2 131072
#define OFF_BIAS 196608
#define SMEM_PAYLOAD 198144
#define SMEM_BYTES (SMEM_PAYLOAD + 1024)

__device__ __forceinline__ uint32_t smem_u32(const void* p) {
    uint32_t a;
    asm("{ .reg .u64 t; cvta.to.shared.u64 t, %1; cvt.u32.u64 %0, t; }" : "=r"(a) : "l"(p));
    return a;
}

// Tile: 128 rows x 128 bf16 (256B/row, 16 chunks of 16B), XOR-swizzled.
// hi tile at base, lo tile at base + 32768.
__device__ __forceinline__ uint32_t toff(int row, int byteCol) {
    int chunk = byteCol >> 4;
    return (uint32_t)(row * 256 + (((chunk ^ (row & 7)) << 4) | (byteCol & 15)));
}

__device__ __forceinline__ uint32_t pack2(__nv_bfloat16 a, __nv_bfloat16 b) {
    return (uint32_t)__bfloat16_as_ushort(a) | ((uint32_t)__bfloat16_as_ushort(b) << 16);
}

__device__ __forceinline__ void ldsm4(uint32_t r[4], uint32_t addr) {
    asm volatile("ldmatrix.sync.aligned.m8n8.x4.shared.b16 {%0,%1,%2,%3}, [%4];"
                 : "=r"(r[0]), "=r"(r[1]), "=r"(r[2]), "=r"(r[3]) : "r"(addr));
}

__device__ __forceinline__ void mma16816(float* c, const uint32_t a[4],
                                         uint32_t b0, uint32_t b1) {
    asm volatile(
        "mma.sync.aligned.m16n8k16.row.col.f32.bf16.bf16.f32 "
        "{%0,%1,%2,%3}, {%4,%5,%6,%7}, {%8,%9}, {%0,%1,%2,%3};"
        : "+f"(c[0]), "+f"(c[1]), "+f"(c[2]), "+f"(c[3])
        : "r"(a[0]), "r"(a[1]), "r"(a[2]), "r"(a[3]), "r"(b0), "r"(b1));
}

// Pre-split + pre-swizzled weights: per W, 32KB hi image + 32KB lo image.
__device__ __align__(16) __nv_bfloat16 g_Wsw[3 * 2 * 16384];

__global__ void prep_weights(const float* __restrict__ Wq, const float* __restrict__ Wk,
                             const float* __restrict__ Wv) {
    int idx = blockIdx.x * blockDim.x + threadIdx.x;
    if (idx >= 3 * 16384) return;
    int t = idx >> 14;
    int rc = idx & 16383;                    // d*128 + e
    const float* W = (t == 0) ? Wq : ((t == 1) ? Wk : Wv);
    float v = W[rc];
    __nv_bfloat16 h = __float2bfloat16_rn(v);
    __nv_bfloat16 l = __float2bfloat16_rn(v - __bfloat162float(h));
    uint32_t o = toff(rc >> 7, (rc & 127) * 2) >> 1;   // bf16 index in image
    g_Wsw[(2 * t) * 16384 + o] = h;
    g_Wsw[(2 * t + 1) * 16384 + o] = l;
}

__device__ __forceinline__ void copy_w(char* dst, int widx, int tid) {
    const uint4* s4 = reinterpret_cast<const uint4*>(g_Wsw + (size_t)widx * 32768);
    uint4* d4 = reinterpret_cast<uint4*>(dst);
#pragma unroll
    for (int i = 0; i < 32; i++) d4[tid + i * 128] = s4[tid + i * 128];
}

// C = A(128x128) * B^T(128x128), 3-term bf16 split, fp32 accum.
// A rows for this warp = [wid*32, wid*32+32). B^T rows (= n) cover 0..127.
__device__ __forceinline__ void gemm128(float (&c)[2][16][4],
                                        uint32_t aBase, uint32_t bBase,
                                        int wid, int arl, int acb, int brl, int bcb) {
#pragma unroll
    for (int mt = 0; mt < 2; mt++)
#pragma unroll
        for (int nt = 0; nt < 16; nt++)
#pragma unroll
            for (int i = 0; i < 4; i++) c[mt][nt][i] = 0.0f;

#pragma unroll 1
    for (int kt = 0; kt < 8; kt++) {
        uint32_t ah[2][4], al[2][4];
#pragma unroll
        for (int mt = 0; mt < 2; mt++) {
            int row = wid * 32 + mt * 16 + arl;
            int chunk = kt * 2 + acb;
            uint32_t off = (uint32_t)(row * 256 + ((chunk ^ (row & 7)) << 4));
            ldsm4(ah[mt], aBase + off);
            ldsm4(al[mt], aBase + 32768u + off);
        }
#pragma unroll
        for (int ng = 0; ng < 8; ng++) {
            int row = ng * 16 + brl;
            int chunk = kt * 2 + bcb;
            uint32_t off = (uint32_t)(row * 256 + ((chunk ^ (row & 7)) << 4));
            uint32_t bh[4], bl[4];
            ldsm4(bh, bBase + off);
            ldsm4(bl, bBase + 32768u + off);
#pragma unroll
            for (int mt = 0; mt < 2; mt++) {
#pragma unroll
                for (int s = 0; s < 2; s++) {
                    float* cc = c[mt][ng * 2 + s];
                    mma16816(cc, ah[mt], bh[2 * s], bh[2 * s + 1]);
                    mma16816(cc, ah[mt], bl[2 * s], bl[2 * s + 1]);
                    mma16816(cc, al[mt], bh[2 * s], bh[2 * s + 1]);
                }
            }
        }
    }
}

__device__ __forceinline__ void store_pair(char* dst, int row, int col, float v0, float v1) {
    __nv_bfloat16 h0 = __float2bfloat16_rn(v0), h1 = __float2bfloat16_rn(v1);
    uint32_t off = toff(row, col * 2);
    *reinterpret_cast<uint32_t*>(dst + off) = pack2(h0, h1);
    *reinterpret_cast<uint32_t*>(dst + 32768 + off) =
        pack2(__float2bfloat16_rn(v0 - __bfloat162float(h0)),
              __float2bfloat16_rn(v1 - __bfloat162float(h1)));
}

// epilogue: C + bias[col] -> bf16 hi/lo tile
__device__ __forceinline__ void epi_colbias(const float (&c)[2][16][4], char* dst,
                                            const float* bias, int wid, int rq, int cq) {
#pragma unroll
    for (int nt = 0; nt < 16; nt++) {
        int col = nt * 8 + cq;
        float b0 = bias[col], b1 = bias[col + 1];
#pragma unroll
        for (int mt = 0; mt < 2; mt++)
#pragma unroll
            for (int h = 0; h < 2; h++) {
                int row = wid * 32 + mt * 16 + h * 8 + rq;
                store_pair(dst, row, col, c[mt][nt][2 * h] + b0, c[mt][nt][2 * h + 1] + b1);
            }
    }
}

// epilogue: C + bias[row] -> bf16 hi/lo tile (for vT, row = d)
__device__ __forceinline__ void epi_rowbias(const float (&c)[2][16][4], char* dst,
                                            const float* bias, int wid, int rq, int cq) {
#pragma unroll
    for (int mt = 0; mt < 2; mt++)
#pragma unroll
        for (int h = 0; h < 2; h++) {
            int row = wid * 32 + mt * 16 + h * 8 + rq;
            float br = bias[row];
#pragma unroll
            for (int nt = 0; nt < 16; nt++) {
                int col = nt * 8 + cq;
                store_pair(dst, row, col, c[mt][nt][2 * h] + br, c[mt][nt][2 * h + 1] + br);
            }
        }
}

// epilogue without bias (P) -> bf16 hi/lo tile
__device__ __forceinline__ void epi_nobias(const float (&c)[2][16][4], char* dst,
                                           int wid, int rq, int cq) {
#pragma unroll
    for (int nt = 0; nt < 16; nt++) {
        int col = nt * 8 + cq;
#pragma unroll
        for (int mt = 0; mt < 2; mt++)
#pragma unroll
            for (int h = 0; h < 2; h++) {
                int row = wid * 32 + mt * 16 + h * 8 + rq;
                store_pair(dst, row, col, c[mt][nt][2 * h], c[mt][nt][2 * h + 1]);
            }
    }
}

__global__ void __launch_bounds__(128, 1)
win_attn(const float* __restrict__ x, const float* __restrict__ bq,
         const float* __restrict__ bk, const float* __restrict__ bv,
         float* __restrict__ out, int nwin) {
    extern __shared__ char smem_raw[];
    uint32_t sraw = smem_u32(smem_raw);
    uint32_t sb = (sraw + 1023u) & ~1023u;
    char* smem = smem_raw + (sb - sraw);

    const int tid = threadIdx.x, wid = tid >> 5, lane = tid & 31;

    float* sbq = reinterpret_cast<float*>(smem + OFF_BIAS);
    float* sbk = sbq + 128;
    float* sbv = sbq + 256;
    sbq[tid] = bq[tid];
    sbk[tid] = bk[tid];
    sbv[tid] = bv[tid];
    __syncthreads();

    // ldmatrix lane mappings
    const int arl = (lane & 7) + ((lane >> 3) & 1) * 8, acb = (lane >> 4) & 1;
    const int brl = (lane & 7) + ((lane >> 4) & 1) * 8, bcb = (lane >> 3) & 1;
    const int rq = lane >> 2, cq = 2 * (lane & 3);

    float c[2][16][4];

    for (int w = blockIdx.x; w < nwin; w += gridDim.x) {
        const float* xw = x + (size_t)w * (WIN * 128);

        // ---- load + split x into xbuf ----
#pragma unroll
        for (int i = 0; i < 32; i++) {
            int idx4 = i * 128 + tid;
            int row = idx4 >> 5, col4 = idx4 & 31;     // 4 floats per col4
            float4 v = reinterpret_cast<const float4*>(xw)[idx4];
            __nv_bfloat16 h0 = __float2bfloat16_rn(v.x), h1 = __float2bfloat16_rn(v.y);
            __nv_bfloat16 h2 = __float2bfloat16_rn(v.z), h3 = __float2bfloat16_rn(v.w);
            uint32_t off = toff(row, col4 * 8);
            *reinterpret_cast<uint2*>(smem + XBUF + off) =
                make_uint2(pack2(h0, h1), pack2(h2, h3));
            *reinterpret_cast<uint2*>(smem + XBUF + 32768 + off) = make_uint2(
                pack2(__float2bfloat16_rn(v.x - __bfloat162float(h0)),
                      __float2bfloat16_rn(v.y - __bfloat162float(h1))),
                pack2(__float2bfloat16_rn(v.z - __bfloat162float(h2)),
                      __float2bfloat16_rn(v.w - __bfloat162float(h3))));
        }
        copy_w(smem + WBUF, 0, tid);   // Wq
        __syncthreads();

        // ---- q = x Wq^T + bq -> buf2 ----
        gemm128(c, sb + XBUF, sb + WBUF, wid, arl, acb, brl, bcb);
        epi_colbias(c, smem + BUF2, sbq, wid, rq, cq);
        __syncthreads();

        // ---- k = x Wk^T + bk -> wbuf ----
        copy_w(smem + WBUF, 1, tid);   // Wk
        __syncthreads();
        gemm128(c, sb + XBUF, sb + WBUF, wid, arl, acb, brl, bcb);
        __syncthreads();               // all warps done reading Wk
        epi_colbias(c, smem + WBUF, sbk, wid, rq, cq);
        __syncthreads();

        // ---- S = q k^T ; softmax ; P -> buf2 ----
        gemm128(c, sb + BUF2, sb + WBUF, wid, arl, acb, brl, bcb);
#pragma unroll
        for (int mt = 0; mt < 2; mt++) {
#pragma unroll
            for (int h = 0; h < 2; h++) {
                float m = -1e30f;
#pragma unroll
                for (int nt = 0; nt < 16; nt++)
                    m = fmaxf(m, fmaxf(c[mt][nt][2 * h], c[mt][nt][2 * h + 1]));
                m = fmaxf(m, __shfl_xor_sync(0xffffffffu, m, 1));
                m = fmaxf(m, __shfl_xor_sync(0xffffffffu, m, 2));
                float s = 0.0f;
#pragma unroll
                for (int nt = 0; nt < 16; nt++) {
                    float e0 = __expf(c[mt][nt][2 * h] - m);
                    float e1 = __expf(c[mt][nt][2 * h + 1] - m);
                    c[mt][nt][2 * h] = e0;
                    c[mt][nt][2 * h + 1] = e1;
                    s += e0 + e1;
                }
                s += __shfl_xor_sync(0xffffffffu, s, 1);
                s += __shfl_xor_sync(0xffffffffu, s, 2);
                float inv = 1.0f / s;
#pragma unroll
                for (int nt = 0; nt < 16; nt++) {
                    c[mt][nt][2 * h] *= inv;
                    c[mt][nt][2 * h + 1] *= inv;
                }
            }
        }
        epi_nobias(c, smem + BUF2, wid, rq, cq);   // P (own rows; q dead)
        __syncthreads();                           // all warps done reading k

        // ---- vT = Wv x^T (+bv per row d) -> xbuf ----
        copy_w(smem + WBUF, 2, tid);   // Wv
        __syncthreads();
        gemm128(c, sb + WBUF, sb + XBUF, wid, arl, acb, brl, bcb);
        __syncthreads();               // all warps done reading x
        epi_rowbias(c, smem + XBUF, sbv, wid, rq, cq);
        __syncthreads();

        // ---- O = P vT^T -> out ----
        gemm128(c, sb + BUF2, sb + XBUF, wid, arl, acb, brl, bcb);
        {
            float* outw = out + (size_t)w * (WIN * 128);
#pragma unroll
            for (int mt = 0; mt < 2; mt++)
#pragma unroll
                for (int h = 0; h < 2; h++) {
                    int row = wid * 32 + mt * 16 + h * 8 + rq;
#pragma unroll
                    for (int nt = 0; nt < 16; nt++) {
                        int col = nt * 8 + cq;
                        *reinterpret_cast<float2*>(outw + row * 128 + col) =
                            make_float2(c[mt][nt][2 * h], c[mt][nt][2 * h + 1]);
                    }
                }
        }
        __syncthreads();   // protect xbuf/buf2 before next window
    }
}

extern "C" void kernel_launch(void* const* d_in, const int* in_sizes, int n_in,
                              void* d_out, int out_size) {
    const float* x  = (const float*)d_in[0];
    const float* Wq = (const float*)d_in[1];
    const float* bq = (const float*)d_in[2];
    const float* Wk = (const float*)d_in[3];
    const float* bk = (const float*)d_in[4];
    const float* Wv = (const float*)d_in[5];
    const float* bv = (const float*)d_in[6];
    float* out = (float*)d_out;

    int nwin = in_sizes[0] / (WIN * 128);

    prep_weights<<<192, 256>>>(Wq, Wk, Wv);

    cudaFuncSetAttribute(win_attn, cudaFuncAttributeMaxDynamicSharedMemorySize, SMEM_BYTES);
    int grid = nwin < 148 ? nwin : 148;
    win_attn<<<grid, 128, SMEM_BYTES>>>(x, bq, bk, bv, out, nwin);
}

// round 5
// speedup vs baseline: 1.1735x; 1.1735x over previous
#include <cuda_runtime.h>
#include <cuda_bf16.h>
#include <cstdint>
#include <cstddef>

// ============================================================================
// Windowed self-attention via mma.sync.m16n8k16 bf16 (3-term split, fp32 acc).
// Softmax-invariance trick: S = x (Wq^T Wk) x^T + const_row + w_col, so only
// 4 GEMMs per window: t = x M^T, S = t x^T (+w col bias), vT = Wv x^T + bv,
// O = P vT^T.  8 warps x 16 rows each, 256 threads, persistent CTAs.
// ============================================================================

#define WIN 128
#define XBUF 0
#define WBUF 65536
#define BUF2 131072
#define OFF_BV 196608          // 128 floats
#define OFF_R  197120          // 128 floats
#define OFF_W  197632          // 128 floats
#define SMEM_PAYLOAD 198144
#define SMEM_BYTES (SMEM_PAYLOAD + 1024)

__device__ __forceinline__ uint32_t smem_u32(const void* p) {
    uint32_t a;
    asm("{ .reg .u64 t; cvta.to.shared.u64 t, %1; cvt.u32.u64 %0, t; }" : "=r"(a) : "l"(p));
    return a;
}

// Tile: 128 rows x 128 bf16 (256B/row, 16 chunks of 16B), XOR-swizzled.
// hi tile at base, lo tile at base + 32768.
__device__ __forceinline__ uint32_t toff(int row, int byteCol) {
    int chunk = byteCol >> 4;
    return (uint32_t)(row * 256 + (((chunk ^ (row & 7)) << 4) | (byteCol & 15)));
}

__device__ __forceinline__ uint32_t pack2(__nv_bfloat16 a, __nv_bfloat16 b) {
    return (uint32_t)__bfloat16_as_ushort(a) | ((uint32_t)__bfloat16_as_ushort(b) << 16);
}

__device__ __forceinline__ void ldsm4(uint32_t r[4], uint32_t addr) {
    asm volatile("ldmatrix.sync.aligned.m8n8.x4.shared.b16 {%0,%1,%2,%3}, [%4];"
                 : "=r"(r[0]), "=r"(r[1]), "=r"(r[2]), "=r"(r[3]) : "r"(addr));
}

__device__ __forceinline__ void mma16816(float* c, const uint32_t a[4],
                                         uint32_t b0, uint32_t b1) {
    asm volatile(
        "mma.sync.aligned.m16n8k16.row.col.f32.bf16.bf16.f32 "
        "{%0,%1,%2,%3}, {%4,%5,%6,%7}, {%8,%9}, {%0,%1,%2,%3};"
        : "+f"(c[0]), "+f"(c[1]), "+f"(c[2]), "+f"(c[3])
        : "r"(a[0]), "r"(a[1]), "r"(a[2]), "r"(a[3]), "r"(b0), "r"(b1));
}

// Pre-split + pre-swizzled images: [M^T hi, M^T lo, Wv hi, Wv lo]
__device__ __align__(16) __nv_bfloat16 g_img[4 * 16384];
__device__ float g_r[128];

// ---- prep: M[e,f] = sum_d Wq[d,e] Wk[d,f]; store as B-image row f, col e ----
__global__ void prep_m(const float* __restrict__ Wq, const float* __restrict__ Wk) {
    int f = blockIdx.x, e = threadIdx.x;
    float acc = 0.0f;
#pragma unroll 4
    for (int d = 0; d < 128; d++)
        acc += Wq[d * 128 + e] * Wk[d * 128 + f];
    __nv_bfloat16 h = __float2bfloat16_rn(acc);
    __nv_bfloat16 l = __float2bfloat16_rn(acc - __bfloat162float(h));
    uint32_t o = toff(f, e * 2) >> 1;
    g_img[o] = h;
    g_img[16384 + o] = l;
}

// ---- prep: r[f] = sum_d bq[d] Wk[d,f] ----
__global__ void prep_r(const float* __restrict__ bq, const float* __restrict__ Wk) {
    int f = threadIdx.x;
    float acc = 0.0f;
#pragma unroll 4
    for (int d = 0; d < 128; d++)
        acc += bq[d] * Wk[d * 128 + f];
    g_r[f] = acc;
}

// ---- prep: Wv split image ----
__global__ void prep_wv(const float* __restrict__ Wv) {
    int d = blockIdx.x, e = threadIdx.x;
    float v = Wv[d * 128 + e];
    __nv_bfloat16 h = __float2bfloat16_rn(v);
    __nv_bfloat16 l = __float2bfloat16_rn(v - __bfloat162float(h));
    uint32_t o = toff(d, e * 2) >> 1;
    g_img[2 * 16384 + o] = h;
    g_img[3 * 16384 + o] = l;
}

// copy one pre-swizzled hi+lo image pair (64KB) into smem region (256 threads)
__device__ __forceinline__ void copy_img(char* dst, int widx, int tid) {
    const uint4* s4 = reinterpret_cast<const uint4*>(g_img + (size_t)widx * 32768);
    uint4* d4 = reinterpret_cast<uint4*>(dst);
#pragma unroll
    for (int i = 0; i < 16; i++) d4[tid + i * 256] = s4[tid + i * 256];
}

// C = A(own 16 rows) * B^T(128x128), 3-term bf16 split, fp32 accum.
__device__ __forceinline__ void gemm128(float (&c)[16][4],
                                        uint32_t aBase, uint32_t bBase,
                                        int arow, int acb, int brl, int bcb) {
#pragma unroll
    for (int nt = 0; nt < 16; nt++)
#pragma unroll
        for (int i = 0; i < 4; i++) c[nt][i] = 0.0f;

#pragma unroll 1
    for (int kt = 0; kt < 8; kt++) {
        uint32_t ah[4], al[4];
        {
            uint32_t off = (uint32_t)(arow * 256 + (((kt * 2 + acb) ^ (arow & 7)) << 4));
            ldsm4(ah, aBase + off);
            ldsm4(al, aBase + 32768u + off);
        }
#pragma unroll
        for (int ng = 0; ng < 8; ng++) {
            int brow = ng * 16 + brl;
            uint32_t boff = (uint32_t)(brow * 256 + (((kt * 2 + bcb) ^ (brow & 7)) << 4));
            uint32_t bh[4], bl[4];
            ldsm4(bh, bBase + boff);
            ldsm4(bl, bBase + 32768u + boff);
#pragma unroll
            for (int s = 0; s < 2; s++) {
                float* cc = c[ng * 2 + s];
                mma16816(cc, ah, bh[2 * s], bh[2 * s + 1]);
                mma16816(cc, ah, bl[2 * s], bl[2 * s + 1]);
                mma16816(cc, al, bh[2 * s], bh[2 * s + 1]);
            }
        }
    }
}

__device__ __forceinline__ void store_pair(char* dst, int row, int col, float v0, float v1) {
    __nv_bfloat16 h0 = __float2bfloat16_rn(v0), h1 = __float2bfloat16_rn(v1);
    uint32_t off = toff(row, col * 2);
    *reinterpret_cast<uint32_t*>(dst + off) = pack2(h0, h1);
    *reinterpret_cast<uint32_t*>(dst + 32768 + off) =
        pack2(__float2bfloat16_rn(v0 - __bfloat162float(h0)),
              __float2bfloat16_rn(v1 - __bfloat162float(h1)));
}

// epilogue without bias -> bf16 hi/lo tile (own 16 rows)
__device__ __forceinline__ void epi_nobias(const float (&c)[16][4], char* dst,
                                           int rowBase, int rq, int cq) {
#pragma unroll
    for (int nt = 0; nt < 16; nt++) {
        int col = nt * 8 + cq;
#pragma unroll
        for (int h = 0; h < 2; h++)
            store_pair(dst, rowBase + h * 8 + rq, col, c[nt][2 * h], c[nt][2 * h + 1]);
    }
}

// epilogue with per-row bias (for vT, row = d)
__device__ __forceinline__ void epi_rowbias(const float (&c)[16][4], char* dst,
                                            const float* bias, int rowBase, int rq, int cq) {
#pragma unroll
    for (int h = 0; h < 2; h++) {
        int row = rowBase + h * 8 + rq;
        float br = bias[row];
#pragma unroll
        for (int nt = 0; nt < 16; nt++) {
            int col = nt * 8 + cq;
            store_pair(dst, row, col, c[nt][2 * h] + br, c[nt][2 * h + 1] + br);
        }
    }
}

__global__ void __launch_bounds__(256, 1)
win_attn(const float* __restrict__ x, const float* __restrict__ bv,
         float* __restrict__ out, int nwin) {
    extern __shared__ char smem_raw[];
    uint32_t sraw = smem_u32(smem_raw);
    uint32_t sb = (sraw + 1023u) & ~1023u;
    char* smem = smem_raw + (sb - sraw);

    const int tid = threadIdx.x, wid = tid >> 5, lane = tid & 31;

    float* sbv = reinterpret_cast<float*>(smem + OFF_BV);
    float* sr  = reinterpret_cast<float*>(smem + OFF_R);
    float* sw  = reinterpret_cast<float*>(smem + OFF_W);
    if (tid < 128) {
        sbv[tid] = bv[tid];
        sr[tid] = g_r[tid];
    }
    __syncthreads();

    // ldmatrix lane mappings
    const int arl = (lane & 7) + ((lane >> 3) & 1) * 8, acb = (lane >> 4) & 1;
    const int brl = (lane & 7) + ((lane >> 4) & 1) * 8, bcb = (lane >> 3) & 1;
    const int rq = lane >> 2, cq = 2 * (lane & 3);
    const int rowBase = wid * 16;
    const int arow = rowBase + arl;

    float rfrag0 = sr[lane * 4], rfrag1 = sr[lane * 4 + 1];
    float rfrag2 = sr[lane * 4 + 2], rfrag3 = sr[lane * 4 + 3];

    float c[16][4];

    for (int w = blockIdx.x; w < nwin; w += gridDim.x) {
        const float* xw = x + (size_t)w * (WIN * 128);

        // ---- phase A: load + split x into xbuf; M image -> wbuf; w vector ----
#pragma unroll
        for (int i = 0; i < 16; i++) {
            int idx4 = i * 256 + tid;
            int row = idx4 >> 5, col4 = idx4 & 31;
            float4 v = reinterpret_cast<const float4*>(xw)[idx4];
            __nv_bfloat16 h0 = __float2bfloat16_rn(v.x), h1 = __float2bfloat16_rn(v.y);
            __nv_bfloat16 h2 = __float2bfloat16_rn(v.z), h3 = __float2bfloat16_rn(v.w);
            uint32_t off = toff(row, col4 * 8);
            *reinterpret_cast<uint2*>(smem + XBUF + off) =
                make_uint2(pack2(h0, h1), pack2(h2, h3));
            *reinterpret_cast<uint2*>(smem + XBUF + 32768 + off) = make_uint2(
                pack2(__float2bfloat16_rn(v.x - __bfloat162float(h0)),
                      __float2bfloat16_rn(v.y - __bfloat162float(h1))),
                pack2(__float2bfloat16_rn(v.z - __bfloat162float(h2)),
                      __float2bfloat16_rn(v.w - __bfloat162float(h3))));
        }
        copy_img(smem + WBUF, 0, tid);    // M^T image
        // w[j] = r . x_j  (warp per 16 rows, coalesced float4 per lane)
#pragma unroll 1
        for (int jr = 0; jr < 16; jr++) {
            int j = rowBase + jr;
            float4 v = reinterpret_cast<const float4*>(xw)[j * 32 + lane];
            float p = v.x * rfrag0 + v.y * rfrag1 + v.z * rfrag2 + v.w * rfrag3;
            p += __shfl_xor_sync(0xffffffffu, p, 16);
            p += __shfl_xor_sync(0xffffffffu, p, 8);
            p += __shfl_xor_sync(0xffffffffu, p, 4);
            p += __shfl_xor_sync(0xffffffffu, p, 2);
            p += __shfl_xor_sync(0xffffffffu, p, 1);
            if (lane == 0) sw[j] = p;
        }
        __syncthreads();

        // ---- GEMM1: t = x M^T -> buf2 (own rows) ----
        gemm128(c, sb + XBUF, sb + WBUF, arow, acb, brl, bcb);
        epi_nobias(c, smem + BUF2, rowBase, rq, cq);
        __syncwarp();

        // ---- GEMM2: S = t x^T ; softmax(+w col bias) ; P -> buf2 (own rows) ----
        gemm128(c, sb + BUF2, sb + XBUF, arow, acb, brl, bcb);
#pragma unroll
        for (int h = 0; h < 2; h++) {
            float m = -1e30f;
#pragma unroll
            for (int nt = 0; nt < 16; nt++) {
                int col = nt * 8 + cq;
                c[nt][2 * h] += sw[col];
                c[nt][2 * h + 1] += sw[col + 1];
                m = fmaxf(m, fmaxf(c[nt][2 * h], c[nt][2 * h + 1]));
            }
            m = fmaxf(m, __shfl_xor_sync(0xffffffffu, m, 1));
            m = fmaxf(m, __shfl_xor_sync(0xffffffffu, m, 2));
            float s = 0.0f;
#pragma unroll
            for (int nt = 0; nt < 16; nt++) {
                float e0 = __expf(c[nt][2 * h] - m);
                float e1 = __expf(c[nt][2 * h + 1] - m);
                c[nt][2 * h] = e0;
                c[nt][2 * h + 1] = e1;
                s += e0 + e1;
            }
            s += __shfl_xor_sync(0xffffffffu, s, 1);
            s += __shfl_xor_sync(0xffffffffu, s, 2);
            float inv = 1.0f / s;
#pragma unroll
            for (int nt = 0; nt < 16; nt++) {
                c[nt][2 * h] *= inv;
                c[nt][2 * h + 1] *= inv;
            }
        }
        epi_nobias(c, smem + BUF2, rowBase, rq, cq);
        __syncthreads();                   // all warps done with M (wbuf) + t reads

        // ---- Wv image -> wbuf ----
        copy_img(smem + WBUF, 1, tid);
        __syncthreads();

        // ---- GEMM3: vT = Wv x^T (+bv row) -> xbuf ----
        gemm128(c, sb + WBUF, sb + XBUF, arow, acb, brl, bcb);
        __syncthreads();                   // all warps done reading x before overwrite
        epi_rowbias(c, smem + XBUF, sbv, rowBase, rq, cq);
        __syncthreads();

        // ---- GEMM4: O = P vT^T -> out ----
        gemm128(c, sb + BUF2, sb + XBUF, arow, acb, brl, bcb);
        {
            float* outw = out + (size_t)w * (WIN * 128);
#pragma unroll
            for (int h = 0; h < 2; h++) {
                int row = rowBase + h * 8 + rq;
#pragma unroll
                for (int nt = 0; nt < 16; nt++) {
                    int col = nt * 8 + cq;
                    *reinterpret_cast<float2*>(outw + row * 128 + col) =
                        make_float2(c[nt][2 * h], c[nt][2 * h + 1]);
                }
            }
        }
        __syncthreads();                   // protect xbuf/buf2/sw before next window
    }
}

extern "C" void kernel_launch(void* const* d_in, const int* in_sizes, int n_in,
                              void* d_out, int out_size) {
    const float* x  = (const float*)d_in[0];
    const float* Wq = (const float*)d_in[1];
    const float* bq = (const float*)d_in[2];
    const float* Wk = (const float*)d_in[3];
    const float* bv = (const float*)d_in[6];
    const float* Wv = (const float*)d_in[5];
    float* out = (float*)d_out;

    int nwin = in_sizes[0] / (WIN * 128);

    prep_m<<<128, 128>>>(Wq, Wk);
    prep_r<<<1, 128>>>(bq, Wk);
    prep_wv<<<128, 128>>>(Wv);

    cudaFuncSetAttribute(win_attn, cudaFuncAttributeMaxDynamicSharedMemorySize, SMEM_BYTES);
    int grid = nwin < 148 ? nwin : 148;
    win_attn<<<grid, 256, SMEM_BYTES>>>(x, bv, out, nwin);
}

// round 6
// speedup vs baseline: 1.3813x; 1.1770x over previous
#include <cuda_runtime.h>
#include <cuda_bf16.h>
#include <cstdint>
#include <cstddef>

// ============================================================================
// Windowed self-attention via mma.sync.m16n8k16 bf16 (3-term split, fp32 acc).
// S = x (Wq^T Wk) x^T + row_const + w_col  (row_const cancels in softmax) ->
// 4 GEMMs/window: t = x M^T, S = t x^T (+w col), vT = Wv x^T + bv, O = P vT^T.
// t and P stay in registers as mma A-fragments (C->A fragment recycling).
// 8 warps x 16 rows, 256 threads, persistent CTAs.
// ============================================================================

#define WIN 128
#define XBUF 0
#define WBUF 65536
#define VBUF 131072
#define OFF_BV 196608          // 128 floats
#define OFF_R  197120          // 128 floats
#define OFF_W  197632          // 128 floats
#define SMEM_PAYLOAD 198144
#define SMEM_BYTES (SMEM_PAYLOAD + 1024)

__device__ __forceinline__ uint32_t smem_u32(const void* p) {
    uint32_t a;
    asm("{ .reg .u64 t; cvta.to.shared.u64 t, %1; cvt.u32.u64 %0, t; }" : "=r"(a) : "l"(p));
    return a;
}

// Tile: 128 rows x 128 bf16 (256B/row, 16 chunks of 16B), XOR-swizzled.
// hi tile at base, lo tile at base + 32768.
__device__ __forceinline__ uint32_t toff(int row, int byteCol) {
    int chunk = byteCol >> 4;
    return (uint32_t)(row * 256 + (((chunk ^ (row & 7)) << 4) | (byteCol & 15)));
}

__device__ __forceinline__ uint32_t pack2(__nv_bfloat16 a, __nv_bfloat16 b) {
    return (uint32_t)__bfloat16_as_ushort(a) | ((uint32_t)__bfloat16_as_ushort(b) << 16);
}

__device__ __forceinline__ void ldsm4(uint32_t r[4], uint32_t addr) {
    asm volatile("ldmatrix.sync.aligned.m8n8.x4.shared.b16 {%0,%1,%2,%3}, [%4];"
                 : "=r"(r[0]), "=r"(r[1]), "=r"(r[2]), "=r"(r[3]) : "r"(addr));
}

__device__ __forceinline__ void mma16816(float* c, const uint32_t a[4],
                                         uint32_t b0, uint32_t b1) {
    asm volatile(
        "mma.sync.aligned.m16n8k16.row.col.f32.bf16.bf16.f32 "
        "{%0,%1,%2,%3}, {%4,%5,%6,%7}, {%8,%9}, {%0,%1,%2,%3};"
        : "+f"(c[0]), "+f"(c[1]), "+f"(c[2]), "+f"(c[3])
        : "r"(a[0]), "r"(a[1]), "r"(a[2]), "r"(a[3]), "r"(b0), "r"(b1));
}

// Pre-split + pre-swizzled images: [M^T hi, M^T lo, Wv hi, Wv lo]
__device__ __align__(16) __nv_bfloat16 g_img[4 * 16384];
__device__ float g_r[128];

// ---- fused prep: M image, Wv image, r vector ----
__global__ void prep_all(const float* __restrict__ Wq, const float* __restrict__ bq,
                         const float* __restrict__ Wk, const float* __restrict__ Wv) {
    __shared__ float wkcol[128];
    __shared__ float red[4];
    int f = blockIdx.x, e = threadIdx.x;
    wkcol[e] = Wk[e * 128 + f];
    __syncthreads();
    // M[e,f] = sum_d Wq[d,e] Wk[d,f]  -> B-image row f, col e
    float acc = 0.0f;
#pragma unroll 8
    for (int d = 0; d < 128; d++)
        acc += Wq[d * 128 + e] * wkcol[d];
    uint32_t o = toff(f, e * 2) >> 1;
    {
        __nv_bfloat16 h = __float2bfloat16_rn(acc);
        g_img[o] = h;
        g_img[16384 + o] = __float2bfloat16_rn(acc - __bfloat162float(h));
    }
    // Wv image: row f(=d), col e
    {
        float v = Wv[f * 128 + e];
        __nv_bfloat16 h = __float2bfloat16_rn(v);
        g_img[2 * 16384 + o] = h;
        g_img[3 * 16384 + o] = __float2bfloat16_rn(v - __bfloat162float(h));
    }
    // r[f] = sum_d bq[d] Wk[d,f]
    float p = bq[e] * wkcol[e];
#pragma unroll
    for (int m = 16; m >= 1; m >>= 1) p += __shfl_xor_sync(0xffffffffu, p, m);
    if ((e & 31) == 0) red[e >> 5] = p;
    __syncthreads();
    if (e == 0) g_r[f] = red[0] + red[1] + red[2] + red[3];
}

// copy one pre-swizzled hi+lo image pair (64KB) into smem region (256 threads)
__device__ __forceinline__ void copy_img(char* dst, int widx, int tid) {
    const uint4* s4 = reinterpret_cast<const uint4*>(g_img + (size_t)widx * 32768);
    uint4* d4 = reinterpret_cast<uint4*>(dst);
#pragma unroll
    for (int i = 0; i < 16; i++) d4[tid + i * 256] = s4[tid + i * 256];
}

// C = A(own 16 rows via ldsm) * B^T(128x128), 3-term bf16 split, fp32 accum.
__device__ __forceinline__ void gemm128(float (&c)[16][4],
                                        uint32_t aBase, uint32_t bBase,
                                        int arow, int acb, int brl, int bcb) {
#pragma unroll
    for (int nt = 0; nt < 16; nt++)
#pragma unroll
        for (int i = 0; i < 4; i++) c[nt][i] = 0.0f;

#pragma unroll 1
    for (int kt = 0; kt < 8; kt++) {
        uint32_t ah[4], al[4];
        {
            uint32_t off = (uint32_t)(arow * 256 + (((kt * 2 + acb) ^ (arow & 7)) << 4));
            ldsm4(ah, aBase + off);
            ldsm4(al, aBase + 32768u + off);
        }
#pragma unroll
        for (int ng = 0; ng < 8; ng++) {
            int brow = ng * 16 + brl;
            uint32_t boff = (uint32_t)(brow * 256 + (((kt * 2 + bcb) ^ (brow & 7)) << 4));
            uint32_t bh[4], bl[4];
            ldsm4(bh, bBase + boff);
            ldsm4(bl, bBase + 32768u + boff);
#pragma unroll
            for (int s = 0; s < 2; s++) {
                float* cc = c[ng * 2 + s];
                mma16816(cc, ah, bh[2 * s], bh[2 * s + 1]);
                mma16816(cc, ah, bl[2 * s], bl[2 * s + 1]);
                mma16816(cc, al, bh[2 * s], bh[2 * s + 1]);
            }
        }
    }
}

// C = A(register fragments, own 16 rows) * B^T(128x128), 3-term split.
__device__ __forceinline__ void gemm128_regA(float (&c)[16][4],
                                             const uint32_t (&th)[16][2],
                                             const uint32_t (&tl)[16][2],
                                             uint32_t bBase, int brl, int bcb) {
#pragma unroll
    for (int nt = 0; nt < 16; nt++)
#pragma unroll
        for (int i = 0; i < 4; i++) c[nt][i] = 0.0f;

#pragma unroll
    for (int kt = 0; kt < 8; kt++) {
        uint32_t ah[4] = {th[2 * kt][0], th[2 * kt][1], th[2 * kt + 1][0], th[2 * kt + 1][1]};
        uint32_t al[4] = {tl[2 * kt][0], tl[2 * kt][1], tl[2 * kt + 1][0], tl[2 * kt + 1][1]};
#pragma unroll
        for (int ng = 0; ng < 8; ng++) {
            int brow = ng * 16 + brl;
            uint32_t boff = (uint32_t)(brow * 256 + (((kt * 2 + bcb) ^ (brow & 7)) << 4));
            uint32_t bh[4], bl[4];
            ldsm4(bh, bBase + boff);
            ldsm4(bl, bBase + 32768u + boff);
#pragma unroll
            for (int s = 0; s < 2; s++) {
                float* cc = c[ng * 2 + s];
                mma16816(cc, ah, bh[2 * s], bh[2 * s + 1]);
                mma16816(cc, ah, bl[2 * s], bl[2 * s + 1]);
                mma16816(cc, al, bh[2 * s], bh[2 * s + 1]);
            }
        }
    }
}

// pack C fragments (rows = this warp's A rows, cols = next-GEMM k) into
// hi/lo bf16 A-fragments: a = {h[2kt][0], h[2kt][1], h[2kt+1][0], h[2kt+1][1]}
__device__ __forceinline__ void pack_split(const float (&c)[16][4],
                                           uint32_t (&h)[16][2], uint32_t (&l)[16][2]) {
#pragma unroll
    for (int nt = 0; nt < 16; nt++)
#pragma unroll
        for (int j = 0; j < 2; j++) {
            float v0 = c[nt][2 * j], v1 = c[nt][2 * j + 1];
            __nv_bfloat16 h0 = __float2bfloat16_rn(v0), h1 = __float2bfloat16_rn(v1);
            h[nt][j] = pack2(h0, h1);
            l[nt][j] = pack2(__float2bfloat16_rn(v0 - __bfloat162float(h0)),
                             __float2bfloat16_rn(v1 - __bfloat162float(h1)));
        }
}

__device__ __forceinline__ void store_pair(char* dst, int row, int col, float v0, float v1) {
    __nv_bfloat16 h0 = __float2bfloat16_rn(v0), h1 = __float2bfloat16_rn(v1);
    uint32_t off = toff(row, col * 2);
    *reinterpret_cast<uint32_t*>(dst + off) = pack2(h0, h1);
    *reinterpret_cast<uint32_t*>(dst + 32768 + off) =
        pack2(__float2bfloat16_rn(v0 - __bfloat162float(h0)),
              __float2bfloat16_rn(v1 - __bfloat162float(h1)));
}

// epilogue with per-row bias (for vT, row = d)
__device__ __forceinline__ void epi_rowbias(const float (&c)[16][4], char* dst,
                                            const float* bias, int rowBase, int rq, int cq) {
#pragma unroll
    for (int h = 0; h < 2; h++) {
        int row = rowBase + h * 8 + rq;
        float br = bias[row];
#pragma unroll
        for (int nt = 0; nt < 16; nt++) {
            int col = nt * 8 + cq;
            store_pair(dst, row, col, c[nt][2 * h] + br, c[nt][2 * h + 1] + br);
        }
    }
}

__global__ void __launch_bounds__(256, 1)
win_attn(const float* __restrict__ x, const float* __restrict__ bv,
         float* __restrict__ out, int nwin) {
    extern __shared__ char smem_raw[];
    uint32_t sraw = smem_u32(smem_raw);
    uint32_t sb = (sraw + 1023u) & ~1023u;
    char* smem = smem_raw + (sb - sraw);

    const int tid = threadIdx.x, wid = tid >> 5, lane = tid & 31;

    float* sbv = reinterpret_cast<float*>(smem + OFF_BV);
    float* sr  = reinterpret_cast<float*>(smem + OFF_R);
    float* sw  = reinterpret_cast<float*>(smem + OFF_W);
    if (tid < 128) {
        sbv[tid] = bv[tid];
        sr[tid] = g_r[tid];
    }
    __syncthreads();

    // ldmatrix lane mappings
    const int arl = (lane & 7) + ((lane >> 3) & 1) * 8, acb = (lane >> 4) & 1;
    const int brl = (lane & 7) + ((lane >> 4) & 1) * 8, bcb = (lane >> 3) & 1;
    const int rq = lane >> 2, cq = 2 * (lane & 3);
    const int rowBase = wid * 16;
    const int arow = rowBase + arl;

    float rfrag0 = sr[lane * 4], rfrag1 = sr[lane * 4 + 1];
    float rfrag2 = sr[lane * 4 + 2], rfrag3 = sr[lane * 4 + 3];

    float c[16][4];
    uint32_t fh[16][2], fl[16][2];   // A-fragments for t, then P

    for (int w = blockIdx.x; w < nwin; w += gridDim.x) {
        const float* xw = x + (size_t)w * (WIN * 128);

        // ---- phase A: load + split x into xbuf; M image -> wbuf; w vector ----
#pragma unroll
        for (int i = 0; i < 16; i++) {
            int idx4 = i * 256 + tid;
            int row = idx4 >> 5, col4 = idx4 & 31;
            float4 v = reinterpret_cast<const float4*>(xw)[idx4];
            __nv_bfloat16 h0 = __float2bfloat16_rn(v.x), h1 = __float2bfloat16_rn(v.y);
            __nv_bfloat16 h2 = __float2bfloat16_rn(v.z), h3 = __float2bfloat16_rn(v.w);
            uint32_t off = toff(row, col4 * 8);
            *reinterpret_cast<uint2*>(smem + XBUF + off) =
                make_uint2(pack2(h0, h1), pack2(h2, h3));
            *reinterpret_cast<uint2*>(smem + XBUF + 32768 + off) = make_uint2(
                pack2(__float2bfloat16_rn(v.x - __bfloat162float(h0)),
                      __float2bfloat16_rn(v.y - __bfloat162float(h1))),
                pack2(__float2bfloat16_rn(v.z - __bfloat162float(h2)),
                      __float2bfloat16_rn(v.w - __bfloat162float(h3))));
        }
        copy_img(smem + WBUF, 0, tid);    // M^T image
        // w[j] = r . x_j
#pragma unroll 1
        for (int jr = 0; jr < 16; jr++) {
            int j = rowBase + jr;
            float4 v = reinterpret_cast<const float4*>(xw)[j * 32 + lane];
            float p = v.x * rfrag0 + v.y * rfrag1 + v.z * rfrag2 + v.w * rfrag3;
            p += __shfl_xor_sync(0xffffffffu, p, 16);
            p += __shfl_xor_sync(0xffffffffu, p, 8);
            p += __shfl_xor_sync(0xffffffffu, p, 4);
            p += __shfl_xor_sync(0xffffffffu, p, 2);
            p += __shfl_xor_sync(0xffffffffu, p, 1);
            if (lane == 0) sw[j] = p;
        }
        __syncthreads();                 // (1) xbuf, M, sw ready

        // ---- GEMM1: t = x M^T -> register A-fragments ----
        gemm128(c, sb + XBUF, sb + WBUF, arow, acb, brl, bcb);
        pack_split(c, fh, fl);
        __syncthreads();                 // (2) M dead everywhere

        // ---- Wv image -> wbuf (overlaps GEMM2 tensor work across warps) ----
        copy_img(smem + WBUF, 1, tid);

        // ---- GEMM2: S = t x^T ; softmax(+w col bias) ; P -> register frags ----
        gemm128_regA(c, fh, fl, sb + XBUF, brl, bcb);
#pragma unroll
        for (int h = 0; h < 2; h++) {
            float m = -1e30f;
#pragma unroll
            for (int nt = 0; nt < 16; nt++) {
                int col = nt * 8 + cq;
                c[nt][2 * h] += sw[col];
                c[nt][2 * h + 1] += sw[col + 1];
                m = fmaxf(m, fmaxf(c[nt][2 * h], c[nt][2 * h + 1]));
            }
            m = fmaxf(m, __shfl_xor_sync(0xffffffffu, m, 1));
            m = fmaxf(m, __shfl_xor_sync(0xffffffffu, m, 2));
            float s = 0.0f;
#pragma unroll
            for (int nt = 0; nt < 16; nt++) {
                float e0 = __expf(c[nt][2 * h] - m);
                float e1 = __expf(c[nt][2 * h + 1] - m);
                c[nt][2 * h] = e0;
                c[nt][2 * h + 1] = e1;
                s += e0 + e1;
            }
            s += __shfl_xor_sync(0xffffffffu, s, 1);
            s += __shfl_xor_sync(0xffffffffu, s, 2);
            float inv = 1.0f / s;
#pragma unroll
            for (int nt = 0; nt < 16; nt++) {
                c[nt][2 * h] *= inv;
                c[nt][2 * h + 1] *= inv;
            }
        }
        pack_split(c, fh, fl);           // P fragments
        __syncthreads();                 // (3) Wv copy complete; xbuf still live

        // ---- GEMM3: vT = Wv x^T (+bv row) -> vbuf ----
        gemm128(c, sb + WBUF, sb + XBUF, arow, acb, brl, bcb);
        epi_rowbias(c, smem + VBUF, sbv, rowBase, rq, cq);
        __syncthreads();                 // (4) vT visible

        // ---- GEMM4: O = P vT^T -> out ----
        gemm128_regA(c, fh, fl, sb + VBUF, brl, bcb);
        {
            float* outw = out + (size_t)w * (WIN * 128);
#pragma unroll
            for (int h = 0; h < 2; h++) {
                int row = rowBase + h * 8 + rq;
#pragma unroll
                for (int nt = 0; nt < 16; nt++) {
                    int col = nt * 8 + cq;
                    *reinterpret_cast<float2*>(outw + row * 128 + col) =
                        make_float2(c[nt][2 * h], c[nt][2 * h + 1]);
                }
            }
        }
        // no trailing sync needed: next phase A touches only xbuf/wbuf/sw,
        // all of whose readers are behind barrier (4).
    }
}

extern "C" void kernel_launch(void* const* d_in, const int* in_sizes, int n_in,
                              void* d_out, int out_size) {
    const float* x  = (const float*)d_in[0];
    const float* Wq = (const float*)d_in[1];
    const float* bq = (const float*)d_in[2];
    const float* Wk = (const float*)d_in[3];
    const float* Wv = (const float*)d_in[5];
    const float* bv = (const float*)d_in[6];
    float* out = (float*)d_out;

    int nwin = in_sizes[0] / (WIN * 128);

    prep_all<<<128, 128>>>(Wq, bq, Wk, Wv);

    cudaFuncSetAttribute(win_attn, cudaFuncAttributeMaxDynamicSharedMemorySize, SMEM_BYTES);
    int grid = nwin < 148 ? nwin : 148;
    win_attn<<<grid, 256, SMEM_BYTES>>>(x, bv, out, nwin);
}

// round 7
// speedup vs baseline: 1.5628x; 1.1314x over previous
#include <cuda_runtime.h>
#include <cuda_fp16.h>
#include <cstdint>
#include <cstddef>

// ============================================================================
// Windowed self-attention via mma.sync.m16n8k16 fp16 (split-fp32, fp32 acc).
// S = x (Wq^T Wk) x^T + row_const + w_col  (row_const cancels in softmax) ->
// 4 GEMMs/window: t = x M^T (3-term), S = t x^T (3-term, +w col),
// vT = Wv x^T + bv (2-term), O = P vT^T (2-term).
// t and P stay in registers as mma A-fragments. M/Wv images resident in smem.
// 8 warps x 16 rows, 256 threads, persistent CTAs.
// ============================================================================

#define WIN 128
// smem layout (bytes from 1KB-aligned base)
#define XH   0
#define XL   32768
#define MH   65536
#define WVH  131072
#define VTB  196608
#define OFF_BV 229376
#define OFF_R  229888
#define OFF_W  230400
#define SMEM_PAYLOAD 230912
#define SMEM_BYTES (SMEM_PAYLOAD + 1024)

__device__ __forceinline__ uint32_t smem_u32(const void* p) {
    uint32_t a;
    asm("{ .reg .u64 t; cvta.to.shared.u64 t, %1; cvt.u32.u64 %0, t; }" : "=r"(a) : "l"(p));
    return a;
}

// Tile: 128 rows x 128 fp16 (256B/row, 16 chunks of 16B), XOR-swizzled.
__device__ __forceinline__ uint32_t toff(int row, int byteCol) {
    int chunk = byteCol >> 4;
    return (uint32_t)(row * 256 + (((chunk ^ (row & 7)) << 4) | (byteCol & 15)));
}

__device__ __forceinline__ uint32_t pack2h(__half a, __half b) {
    return (uint32_t)__half_as_ushort(a) | ((uint32_t)__half_as_ushort(b) << 16);
}

__device__ __forceinline__ void ldsm4(uint32_t r[4], uint32_t addr) {
    asm volatile("ldmatrix.sync.aligned.m8n8.x4.shared.b16 {%0,%1,%2,%3}, [%4];"
                 : "=r"(r[0]), "=r"(r[1]), "=r"(r[2]), "=r"(r[3]) : "r"(addr));
}

__device__ __forceinline__ void mma16816(float* c, const uint32_t a[4],
                                         uint32_t b0, uint32_t b1) {
    asm volatile(
        "mma.sync.aligned.m16n8k16.row.col.f32.f16.f16.f32 "
        "{%0,%1,%2,%3}, {%4,%5,%6,%7}, {%8,%9}, {%0,%1,%2,%3};"
        : "+f"(c[0]), "+f"(c[1]), "+f"(c[2]), "+f"(c[3])
        : "r"(a[0]), "r"(a[1]), "r"(a[2]), "r"(a[3]), "r"(b0), "r"(b1));
}

// Pre-split + pre-swizzled images: [M^T hi, M^T lo, Wv hi, Wv lo]
__device__ __align__(16) __half g_img[4 * 16384];
__device__ float g_r[128];

// ---- fused prep: M image, Wv image, r vector ----
__global__ void prep_all(const float* __restrict__ Wq, const float* __restrict__ bq,
                         const float* __restrict__ Wk, const float* __restrict__ Wv) {
    __shared__ float wkcol[128];
    __shared__ float red[4];
    int f = blockIdx.x, e = threadIdx.x;
    wkcol[e] = Wk[e * 128 + f];
    __syncthreads();
    // M[e,f] = sum_d Wq[d,e] Wk[d,f]  -> B-image row f, col e
    float acc = 0.0f;
#pragma unroll 8
    for (int d = 0; d < 128; d++)
        acc += Wq[d * 128 + e] * wkcol[d];
    uint32_t o = toff(f, e * 2) >> 1;
    {
        __half h = __float2half_rn(acc);
        g_img[o] = h;
        g_img[16384 + o] = __float2half_rn(acc - __half2float(h));
    }
    // Wv image: row f(=d), col e
    {
        float v = Wv[f * 128 + e];
        __half h = __float2half_rn(v);
        g_img[2 * 16384 + o] = h;
        g_img[3 * 16384 + o] = __float2half_rn(v - __half2float(h));
    }
    // r[f] = sum_d bq[d] Wk[d,f]
    float p = bq[e] * wkcol[e];
#pragma unroll
    for (int m = 16; m >= 1; m >>= 1) p += __shfl_xor_sync(0xffffffffu, p, m);
    if ((e & 31) == 0) red[e >> 5] = p;
    __syncthreads();
    if (e == 0) g_r[f] = red[0] + red[1] + red[2] + red[3];
}

// copy one pre-swizzled hi+lo image pair (64KB) into smem (256 threads)
__device__ __forceinline__ void copy_img64(char* dst, int pairIdx, int tid) {
    const uint4* s4 = reinterpret_cast<const uint4*>(g_img + (size_t)pairIdx * 32768);
    uint4* d4 = reinterpret_cast<uint4*>(dst);
#pragma unroll
    for (int i = 0; i < 16; i++) d4[tid + i * 256] = s4[tid + i * 256];
}

// ---- GEMM variants: C = A(own 16 rows) * B^T(128x128), fp32 accum ----

// 3-term, A from smem (hi at aBase, lo at aBase+32768), B hi/lo
__device__ __forceinline__ void gemm3_sa(float (&c)[16][4],
                                         uint32_t aBase, uint32_t bBase,
                                         int arow, int acb, int brl, int bcb) {
#pragma unroll
    for (int nt = 0; nt < 16; nt++)
#pragma unroll
        for (int i = 0; i < 4; i++) c[nt][i] = 0.0f;
#pragma unroll 1
    for (int kt = 0; kt < 8; kt++) {
        uint32_t ah[4], al[4];
        {
            uint32_t off = (uint32_t)(arow * 256 + (((kt * 2 + acb) ^ (arow & 7)) << 4));
            ldsm4(ah, aBase + off);
            ldsm4(al, aBase + 32768u + off);
        }
#pragma unroll
        for (int ng = 0; ng < 8; ng++) {
            int brow = ng * 16 + brl;
            uint32_t boff = (uint32_t)(brow * 256 + (((kt * 2 + bcb) ^ (brow & 7)) << 4));
            uint32_t bh[4], bl[4];
            ldsm4(bh, bBase + boff);
            ldsm4(bl, bBase + 32768u + boff);
#pragma unroll
            for (int s = 0; s < 2; s++) {
                float* cc = c[ng * 2 + s];
                mma16816(cc, ah, bh[2 * s], bh[2 * s + 1]);
                mma16816(cc, ah, bl[2 * s], bl[2 * s + 1]);
                mma16816(cc, al, bh[2 * s], bh[2 * s + 1]);
            }
        }
    }
}

// 3-term, A from register fragments, B hi/lo
__device__ __forceinline__ void gemm3_ra(float (&c)[16][4],
                                         const uint32_t (&th)[16][2],
                                         const uint32_t (&tl)[16][2],
                                         uint32_t bBase, int brl, int bcb) {
#pragma unroll
    for (int nt = 0; nt < 16; nt++)
#pragma unroll
        for (int i = 0; i < 4; i++) c[nt][i] = 0.0f;
#pragma unroll
    for (int kt = 0; kt < 8; kt++) {
        uint32_t ah[4] = {th[2 * kt][0], th[2 * kt][1], th[2 * kt + 1][0], th[2 * kt + 1][1]};
        uint32_t al[4] = {tl[2 * kt][0], tl[2 * kt][1], tl[2 * kt + 1][0], tl[2 * kt + 1][1]};
#pragma unroll
        for (int ng = 0; ng < 8; ng++) {
            int brow = ng * 16 + brl;
            uint32_t boff = (uint32_t)(brow * 256 + (((kt * 2 + bcb) ^ (brow & 7)) << 4));
            uint32_t bh[4], bl[4];
            ldsm4(bh, bBase + boff);
            ldsm4(bl, bBase + 32768u + boff);
#pragma unroll
            for (int s = 0; s < 2; s++) {
                float* cc = c[ng * 2 + s];
                mma16816(cc, ah, bh[2 * s], bh[2 * s + 1]);
                mma16816(cc, ah, bl[2 * s], bl[2 * s + 1]);
                mma16816(cc, al, bh[2 * s], bh[2 * s + 1]);
            }
        }
    }
}

// 2-term, A smem hi/lo, B single image
__device__ __forceinline__ void gemm2_sa(float (&c)[16][4],
                                         uint32_t aBase, uint32_t bBase,
                                         int arow, int acb, int brl, int bcb) {
#pragma unroll
    for (int nt = 0; nt < 16; nt++)
#pragma unroll
        for (int i = 0; i < 4; i++) c[nt][i] = 0.0f;
#pragma unroll 1
    for (int kt = 0; kt < 8; kt++) {
        uint32_t ah[4], al[4];
        {
            uint32_t off = (uint32_t)(arow * 256 + (((kt * 2 + acb) ^ (arow & 7)) << 4));
            ldsm4(ah, aBase + off);
            ldsm4(al, aBase + 32768u + off);
        }
#pragma unroll
        for (int ng = 0; ng < 8; ng++) {
            int brow = ng * 16 + brl;
            uint32_t boff = (uint32_t)(brow * 256 + (((kt * 2 + bcb) ^ (brow & 7)) << 4));
            uint32_t bh[4];
            ldsm4(bh, bBase + boff);
#pragma unroll
            for (int s = 0; s < 2; s++) {
                float* cc = c[ng * 2 + s];
                mma16816(cc, ah, bh[2 * s], bh[2 * s + 1]);
                mma16816(cc, al, bh[2 * s], bh[2 * s + 1]);
            }
        }
    }
}

// 2-term, A register fragments, B single image
__device__ __forceinline__ void gemm2_ra(float (&c)[16][4],
                                         const uint32_t (&th)[16][2],
                                         const uint32_t (&tl)[16][2],
                                         uint32_t bBase, int brl, int bcb) {
#pragma unroll
    for (int nt = 0; nt < 16; nt++)
#pragma unroll
        for (int i = 0; i < 4; i++) c[nt][i] = 0.0f;
#pragma unroll
    for (int kt = 0; kt < 8; kt++) {
        uint32_t ah[4] = {th[2 * kt][0], th[2 * kt][1], th[2 * kt + 1][0], th[2 * kt + 1][1]};
        uint32_t al[4] = {tl[2 * kt][0], tl[2 * kt][1], tl[2 * kt + 1][0], tl[2 * kt + 1][1]};
#pragma unroll
        for (int ng = 0; ng < 8; ng++) {
            int brow = ng * 16 + brl;
            uint32_t boff = (uint32_t)(brow * 256 + (((kt * 2 + bcb) ^ (brow & 7)) << 4));
            uint32_t bh[4];
            ldsm4(bh, bBase + boff);
#pragma unroll
            for (int s = 0; s < 2; s++) {
                float* cc = c[ng * 2 + s];
                mma16816(cc, ah, bh[2 * s], bh[2 * s + 1]);
                mma16816(cc, al, bh[2 * s], bh[2 * s + 1]);
            }
        }
    }
}

// pack C fragments into hi/lo fp16 A-fragments for the next GEMM
__device__ __forceinline__ void pack_split(const float (&c)[16][4],
                                           uint32_t (&h)[16][2], uint32_t (&l)[16][2]) {
#pragma unroll
    for (int nt = 0; nt < 16; nt++)
#pragma unroll
        for (int j = 0; j < 2; j++) {
            float v0 = c[nt][2 * j], v1 = c[nt][2 * j + 1];
            __half h0 = __float2half_rn(v0), h1 = __float2half_rn(v1);
            h[nt][j] = pack2h(h0, h1);
            l[nt][j] = pack2h(__float2half_rn(v0 - __half2float(h0)),
                              __float2half_rn(v1 - __half2float(h1)));
        }
}

__global__ void __launch_bounds__(256, 1)
win_attn(const float* __restrict__ x, const float* __restrict__ bv,
         float* __restrict__ out, int nwin) {
    extern __shared__ char smem_raw[];
    uint32_t sraw = smem_u32(smem_raw);
    uint32_t sb = (sraw + 1023u) & ~1023u;
    char* smem = smem_raw + (sb - sraw);

    const int tid = threadIdx.x, wid = tid >> 5, lane = tid & 31;

    float* sbv = reinterpret_cast<float*>(smem + OFF_BV);
    float* sr  = reinterpret_cast<float*>(smem + OFF_R);
    float* sw  = reinterpret_cast<float*>(smem + OFF_W);
    if (tid < 128) {
        sbv[tid] = bv[tid];
        sr[tid] = g_r[tid];
    }
    // resident weight images
    copy_img64(smem + MH, 0, tid);
    copy_img64(smem + WVH, 1, tid);
    __syncthreads();

    // ldmatrix lane mappings
    const int arl = (lane & 7) + ((lane >> 3) & 1) * 8, acb = (lane >> 4) & 1;
    const int brl = (lane & 7) + ((lane >> 4) & 1) * 8, bcb = (lane >> 3) & 1;
    const int rq = lane >> 2, cq = 2 * (lane & 3);
    const int rowBase = wid * 16;
    const int arow = rowBase + arl;

    float rfrag0 = sr[lane * 4], rfrag1 = sr[lane * 4 + 1];
    float rfrag2 = sr[lane * 4 + 2], rfrag3 = sr[lane * 4 + 3];

    float c[16][4];
    uint32_t fh[16][2], fl[16][2];   // A-fragments: t, then P

    for (int w = blockIdx.x; w < nwin; w += gridDim.x) {
        const float* xw = x + (size_t)w * (WIN * 128);

        // ---- phase A: load + split x into xh/xl; w vector ----
#pragma unroll
        for (int i = 0; i < 16; i++) {
            int idx4 = i * 256 + tid;
            int row = idx4 >> 5, col4 = idx4 & 31;
            float4 v = reinterpret_cast<const float4*>(xw)[idx4];
            __half h0 = __float2half_rn(v.x), h1 = __float2half_rn(v.y);
            __half h2 = __float2half_rn(v.z), h3 = __float2half_rn(v.w);
            uint32_t off = toff(row, col4 * 8);
            *reinterpret_cast<uint2*>(smem + XH + off) =
                make_uint2(pack2h(h0, h1), pack2h(h2, h3));
            *reinterpret_cast<uint2*>(smem + XL + off) = make_uint2(
                pack2h(__float2half_rn(v.x - __half2float(h0)),
                       __float2half_rn(v.y - __half2float(h1))),
                pack2h(__float2half_rn(v.z - __half2float(h2)),
                       __float2half_rn(v.w - __half2float(h3))));
        }
        // w[j] = r . x_j
#pragma unroll 1
        for (int jr = 0; jr < 16; jr++) {
            int j = rowBase + jr;
            float4 v = reinterpret_cast<const float4*>(xw)[j * 32 + lane];
            float p = v.x * rfrag0 + v.y * rfrag1 + v.z * rfrag2 + v.w * rfrag3;
            p += __shfl_xor_sync(0xffffffffu, p, 16);
            p += __shfl_xor_sync(0xffffffffu, p, 8);
            p += __shfl_xor_sync(0xffffffffu, p, 4);
            p += __shfl_xor_sync(0xffffffffu, p, 2);
            p += __shfl_xor_sync(0xffffffffu, p, 1);
            if (lane == 0) sw[j] = p;
        }
        __syncthreads();                 // (1) xh/xl, sw ready

        // ---- GEMM1 (3-term): t = x M^T -> register fragments ----
        gemm3_sa(c, sb + XH, sb + MH, arow, acb, brl, bcb);
        pack_split(c, fh, fl);

        // ---- GEMM2 (3-term): S = t x^T ; softmax(+w col) ; P -> fragments ----
        gemm3_ra(c, fh, fl, sb + XH, brl, bcb);
#pragma unroll
        for (int h = 0; h < 2; h++) {
            float m = -1e30f;
#pragma unroll
            for (int nt = 0; nt < 16; nt++) {
                int col = nt * 8 + cq;
                c[nt][2 * h] += sw[col];
                c[nt][2 * h + 1] += sw[col + 1];
                m = fmaxf(m, fmaxf(c[nt][2 * h], c[nt][2 * h + 1]));
            }
            m = fmaxf(m, __shfl_xor_sync(0xffffffffu, m, 1));
            m = fmaxf(m, __shfl_xor_sync(0xffffffffu, m, 2));
            float s = 0.0f;
#pragma unroll
            for (int nt = 0; nt < 16; nt++) {
                float e0 = __expf(c[nt][2 * h] - m);
                float e1 = __expf(c[nt][2 * h + 1] - m);
                c[nt][2 * h] = e0;
                c[nt][2 * h + 1] = e1;
                s += e0 + e1;
            }
            s += __shfl_xor_sync(0xffffffffu, s, 1);
            s += __shfl_xor_sync(0xffffffffu, s, 2);
            float inv = 1.0f / s;
#pragma unroll
            for (int nt = 0; nt < 16; nt++) {
                c[nt][2 * h] *= inv;
                c[nt][2 * h + 1] *= inv;
            }
        }
        pack_split(c, fh, fl);           // P fragments

        // ---- GEMM3 (2-term): vT = Wv x^T (+bv row) -> vbuf (single fp16) ----
        gemm2_sa(c, sb + WVH, sb + XH, arow, acb, brl, bcb);
#pragma unroll
        for (int h = 0; h < 2; h++) {
            int row = rowBase + h * 8 + rq;
            float br = sbv[row];
#pragma unroll
            for (int nt = 0; nt < 16; nt++) {
                int col = nt * 8 + cq;
                *reinterpret_cast<uint32_t*>(smem + VTB + toff(row, col * 2)) =
                    pack2h(__float2half_rn(c[nt][2 * h] + br),
                           __float2half_rn(c[nt][2 * h + 1] + br));
            }
        }
        __syncthreads();                 // (2) vT visible to all warps

        // ---- GEMM4 (2-term): O = P vT^T -> out ----
        gemm2_ra(c, fh, fl, sb + VTB, brl, bcb);
        {
            float* outw = out + (size_t)w * (WIN * 128);
#pragma unroll
            for (int h = 0; h < 2; h++) {
                int row = rowBase + h * 8 + rq;
#pragma unroll
                for (int nt = 0; nt < 16; nt++) {
                    int col = nt * 8 + cq;
                    *reinterpret_cast<float2*>(outw + row * 128 + col) =
                        make_float2(c[nt][2 * h], c[nt][2 * h + 1]);
                }
            }
        }
        __syncthreads();                 // (3) protect xh/xl, sw, vbuf
    }
}

extern "C" void kernel_launch(void* const* d_in, const int* in_sizes, int n_in,
                              void* d_out, int out_size) {
    const float* x  = (const float*)d_in[0];
    const float* Wq = (const float*)d_in[1];
    const float* bq = (const float*)d_in[2];
    const float* Wk = (const float*)d_in[3];
    const float* Wv = (const float*)d_in[5];
    const float* bv = (const float*)d_in[6];
    float* out = (float*)d_out;

    int nwin = in_sizes[0] / (WIN * 128);

    prep_all<<<128, 128>>>(Wq, bq, Wk, Wv);

    cudaFuncSetAttribute(win_attn, cudaFuncAttributeMaxDynamicSharedMemorySize, SMEM_BYTES);
    int grid = nwin < 148 ? nwin : 148;
    win_attn<<<grid, 256, SMEM_BYTES>>>(x, bv, out, nwin);
}

// round 8
// speedup vs baseline: 1.6010x; 1.0244x over previous
#include <cuda_runtime.h>
#include <cuda_fp16.h>
#include <cstdint>
#include <cstddef>

// ============================================================================
// Windowed self-attention via mma.sync.m16n8k16 fp16 (split-fp32, fp32 acc).
// S = x (Wq^T Wk) x^T + row_const + w_col  (row_const cancels in softmax) ->
// 4 GEMMs/window: t = x M^T (3-term), S = t x^T (3-term, +w col),
// vT = Wv x^T + bv (2-term), O = P vT^T (2-term).
// G2 and G3 fused in one loop sharing x B-tiles (two accumulation streams).
// t and P stay in registers as mma A-fragments. M/Wv images resident in smem.
// 8 warps x 16 rows, 256 threads, persistent CTAs, 2 barriers/window.
// ============================================================================

#define WIN 128
// smem layout (bytes from 1KB-aligned base)
#define XH   0
#define XL   32768
#define MH   65536
#define WVH  131072
#define VTB  196608
#define OFF_BV 229376
#define OFF_R  229888
#define OFF_W  230400
#define SMEM_PAYLOAD 230912
#define SMEM_BYTES (SMEM_PAYLOAD + 1024)

__device__ __forceinline__ uint32_t smem_u32(const void* p) {
    uint32_t a;
    asm("{ .reg .u64 t; cvta.to.shared.u64 t, %1; cvt.u32.u64 %0, t; }" : "=r"(a) : "l"(p));
    return a;
}

// Tile: 128 rows x 128 fp16 (256B/row, 16 chunks of 16B), XOR-swizzled.
__device__ __forceinline__ uint32_t toff(int row, int byteCol) {
    int chunk = byteCol >> 4;
    return (uint32_t)(row * 256 + (((chunk ^ (row & 7)) << 4) | (byteCol & 15)));
}

__device__ __forceinline__ uint32_t pack2h(__half a, __half b) {
    return (uint32_t)__half_as_ushort(a) | ((uint32_t)__half_as_ushort(b) << 16);
}

__device__ __forceinline__ void ldsm4(uint32_t r[4], uint32_t addr) {
    asm volatile("ldmatrix.sync.aligned.m8n8.x4.shared.b16 {%0,%1,%2,%3}, [%4];"
                 : "=r"(r[0]), "=r"(r[1]), "=r"(r[2]), "=r"(r[3]) : "r"(addr));
}

__device__ __forceinline__ void mma16816(float* c, const uint32_t a[4],
                                         uint32_t b0, uint32_t b1) {
    asm volatile(
        "mma.sync.aligned.m16n8k16.row.col.f32.f16.f16.f32 "
        "{%0,%1,%2,%3}, {%4,%5,%6,%7}, {%8,%9}, {%0,%1,%2,%3};"
        : "+f"(c[0]), "+f"(c[1]), "+f"(c[2]), "+f"(c[3])
        : "r"(a[0]), "r"(a[1]), "r"(a[2]), "r"(a[3]), "r"(b0), "r"(b1));
}

// Pre-split + pre-swizzled images: [M^T hi, M^T lo, Wv hi, Wv lo]
__device__ __align__(16) __half g_img[4 * 16384];
__device__ float g_r[128];

// ---- fused prep: M image, Wv image, r vector ----
__global__ void prep_all(const float* __restrict__ Wq, const float* __restrict__ bq,
                         const float* __restrict__ Wk, const float* __restrict__ Wv) {
    __shared__ float wkcol[128];
    __shared__ float red[4];
    int f = blockIdx.x, e = threadIdx.x;
    wkcol[e] = Wk[e * 128 + f];
    __syncthreads();
    // M[e,f] = sum_d Wq[d,e] Wk[d,f]  -> B-image row f, col e
    float acc = 0.0f;
#pragma unroll 8
    for (int d = 0; d < 128; d++)
        acc += Wq[d * 128 + e] * wkcol[d];
    uint32_t o = toff(f, e * 2) >> 1;
    {
        __half h = __float2half_rn(acc);
        g_img[o] = h;
        g_img[16384 + o] = __float2half_rn(acc - __half2float(h));
    }
    // Wv image: row f(=d), col e
    {
        float v = Wv[f * 128 + e];
        __half h = __float2half_rn(v);
        g_img[2 * 16384 + o] = h;
        g_img[3 * 16384 + o] = __float2half_rn(v - __half2float(h));
    }
    // r[f] = sum_d bq[d] Wk[d,f]
    float p = bq[e] * wkcol[e];
#pragma unroll
    for (int m = 16; m >= 1; m >>= 1) p += __shfl_xor_sync(0xffffffffu, p, m);
    if ((e & 31) == 0) red[e >> 5] = p;
    __syncthreads();
    if (e == 0) g_r[f] = red[0] + red[1] + red[2] + red[3];
}

// copy one pre-swizzled hi+lo image pair (64KB) into smem (256 threads)
__device__ __forceinline__ void copy_img64(char* dst, int pairIdx, int tid) {
    const uint4* s4 = reinterpret_cast<const uint4*>(g_img + (size_t)pairIdx * 32768);
    uint4* d4 = reinterpret_cast<uint4*>(dst);
#pragma unroll
    for (int i = 0; i < 16; i++) d4[tid + i * 256] = s4[tid + i * 256];
}

// ---- GEMM1 (3-term): A smem hi/lo, B smem hi/lo ----
__device__ __forceinline__ void gemm3_sa(float (&c)[16][4],
                                         uint32_t aBase, uint32_t bBase,
                                         int arow, int acb, int brl, int bcb) {
#pragma unroll
    for (int nt = 0; nt < 16; nt++)
#pragma unroll
        for (int i = 0; i < 4; i++) c[nt][i] = 0.0f;
#pragma unroll 1
    for (int kt = 0; kt < 8; kt++) {
        uint32_t ah[4], al[4];
        {
            uint32_t off = (uint32_t)(arow * 256 + (((kt * 2 + acb) ^ (arow & 7)) << 4));
            ldsm4(ah, aBase + off);
            ldsm4(al, aBase + 32768u + off);
        }
#pragma unroll
        for (int ng = 0; ng < 8; ng++) {
            int brow = ng * 16 + brl;
            uint32_t boff = (uint32_t)(brow * 256 + (((kt * 2 + bcb) ^ (brow & 7)) << 4));
            uint32_t bh[4], bl[4];
            ldsm4(bh, bBase + boff);
            ldsm4(bl, bBase + 32768u + boff);
#pragma unroll
            for (int s = 0; s < 2; s++) {
                float* cc = c[ng * 2 + s];
                mma16816(cc, ah, bh[2 * s], bh[2 * s + 1]);
                mma16816(cc, ah, bl[2 * s], bl[2 * s + 1]);
                mma16816(cc, al, bh[2 * s], bh[2 * s + 1]);
            }
        }
    }
}

// ---- fused G2+G3: shared B tiles (x), two accumulation streams ----
// c2: S = t x^T (3-term, A = t register fragments)
// c3: vT = Wv x^T (2-term, A = Wv smem hi/lo)
__device__ __forceinline__ void gemm_g2g3(float (&c2)[16][4], float (&c3)[16][4],
                                          const uint32_t (&th)[16][2],
                                          const uint32_t (&tl)[16][2],
                                          uint32_t xh, uint32_t xl, uint32_t wv,
                                          int arow, int acb, int brl, int bcb) {
#pragma unroll
    for (int nt = 0; nt < 16; nt++)
#pragma unroll
        for (int i = 0; i < 4; i++) { c2[nt][i] = 0.0f; c3[nt][i] = 0.0f; }
#pragma unroll
    for (int kt = 0; kt < 8; kt++) {
        uint32_t ah3[4], al3[4];
        {
            uint32_t aoff = (uint32_t)(arow * 256 + (((kt * 2 + acb) ^ (arow & 7)) << 4));
            ldsm4(ah3, wv + aoff);
            ldsm4(al3, wv + 32768u + aoff);
        }
        uint32_t ah2[4] = {th[2 * kt][0], th[2 * kt][1], th[2 * kt + 1][0], th[2 * kt + 1][1]};
        uint32_t al2[4] = {tl[2 * kt][0], tl[2 * kt][1], tl[2 * kt + 1][0], tl[2 * kt + 1][1]};
#pragma unroll
        for (int ng = 0; ng < 8; ng++) {
            int brow = ng * 16 + brl;
            uint32_t boff = (uint32_t)(brow * 256 + (((kt * 2 + bcb) ^ (brow & 7)) << 4));
            uint32_t bh[4], bl[4];
            ldsm4(bh, xh + boff);
            ldsm4(bl, xl + boff);
#pragma unroll
            for (int s = 0; s < 2; s++) {
                float* cS = c2[ng * 2 + s];
                float* cV = c3[ng * 2 + s];
                mma16816(cS, ah2, bh[2 * s], bh[2 * s + 1]);
                mma16816(cV, ah3, bh[2 * s], bh[2 * s + 1]);
                mma16816(cS, ah2, bl[2 * s], bl[2 * s + 1]);
                mma16816(cV, al3, bh[2 * s], bh[2 * s + 1]);
                mma16816(cS, al2, bh[2 * s], bh[2 * s + 1]);
            }
        }
    }
}

// ---- GEMM4 (2-term): A register fragments, B single image ----
__device__ __forceinline__ void gemm2_ra(float (&c)[16][4],
                                         const uint32_t (&th)[16][2],
                                         const uint32_t (&tl)[16][2],
                                         uint32_t bBase, int brl, int bcb) {
#pragma unroll
    for (int nt = 0; nt < 16; nt++)
#pragma unroll
        for (int i = 0; i < 4; i++) c[nt][i] = 0.0f;
#pragma unroll
    for (int kt = 0; kt < 8; kt++) {
        uint32_t ah[4] = {th[2 * kt][0], th[2 * kt][1], th[2 * kt + 1][0], th[2 * kt + 1][1]};
        uint32_t al[4] = {tl[2 * kt][0], tl[2 * kt][1], tl[2 * kt + 1][0], tl[2 * kt + 1][1]};
#pragma unroll
        for (int ng = 0; ng < 8; ng++) {
            int brow = ng * 16 + brl;
            uint32_t boff = (uint32_t)(brow * 256 + (((kt * 2 + bcb) ^ (brow & 7)) << 4));
            uint32_t bh[4];
            ldsm4(bh, bBase + boff);
#pragma unroll
            for (int s = 0; s < 2; s++) {
                float* cc = c[ng * 2 + s];
                mma16816(cc, ah, bh[2 * s], bh[2 * s + 1]);
                mma16816(cc, al, bh[2 * s], bh[2 * s + 1]);
            }
        }
    }
}

// pack C fragments into hi/lo fp16 A-fragments for the next GEMM
__device__ __forceinline__ void pack_split(const float (&c)[16][4],
                                           uint32_t (&h)[16][2], uint32_t (&l)[16][2]) {
#pragma unroll
    for (int nt = 0; nt < 16; nt++)
#pragma unroll
        for (int j = 0; j < 2; j++) {
            float v0 = c[nt][2 * j], v1 = c[nt][2 * j + 1];
            __half h0 = __float2half_rn(v0), h1 = __float2half_rn(v1);
            h[nt][j] = pack2h(h0, h1);
            l[nt][j] = pack2h(__float2half_rn(v0 - __half2float(h0)),
                              __float2half_rn(v1 - __half2float(h1)));
        }
}

__global__ void __launch_bounds__(256, 1)
win_attn(const float* __restrict__ x, const float* __restrict__ bv,
         float* __restrict__ out, int nwin) {
    extern __shared__ char smem_raw[];
    uint32_t sraw = smem_u32(smem_raw);
    uint32_t sb = (sraw + 1023u) & ~1023u;
    char* smem = smem_raw + (sb - sraw);

    const int tid = threadIdx.x, wid = tid >> 5, lane = tid & 31;

    float* sbv = reinterpret_cast<float*>(smem + OFF_BV);
    float* sr  = reinterpret_cast<float*>(smem + OFF_R);
    float* sw  = reinterpret_cast<float*>(smem + OFF_W);
    if (tid < 128) {
        sbv[tid] = bv[tid];
        sr[tid] = g_r[tid];
    }
    // resident weight images
    copy_img64(smem + MH, 0, tid);
    copy_img64(smem + WVH, 1, tid);
    __syncthreads();

    // ldmatrix lane mappings
    const int arl = (lane & 7) + ((lane >> 3) & 1) * 8, acb = (lane >> 4) & 1;
    const int brl = (lane & 7) + ((lane >> 4) & 1) * 8, bcb = (lane >> 3) & 1;
    const int rq = lane >> 2, cq = 2 * (lane & 3);
    const int rowBase = wid * 16;
    const int arow = rowBase + arl;

    float rfrag0 = sr[lane * 4], rfrag1 = sr[lane * 4 + 1];
    float rfrag2 = sr[lane * 4 + 2], rfrag3 = sr[lane * 4 + 3];

    float c2[16][4], c3[16][4];
    uint32_t fh[16][2], fl[16][2];   // A-fragments: t, then P

    for (int w = blockIdx.x; w < nwin; w += gridDim.x) {
        const float* xw = x + (size_t)w * (WIN * 128);

        // ---- phase A: load + split x into xh/xl; w vector ----
#pragma unroll
        for (int i = 0; i < 16; i++) {
            int idx4 = i * 256 + tid;
            int row = idx4 >> 5, col4 = idx4 & 31;
            float4 v = reinterpret_cast<const float4*>(xw)[idx4];
            __half h0 = __float2half_rn(v.x), h1 = __float2half_rn(v.y);
            __half h2 = __float2half_rn(v.z), h3 = __float2half_rn(v.w);
            uint32_t off = toff(row, col4 * 8);
            *reinterpret_cast<uint2*>(smem + XH + off) =
                make_uint2(pack2h(h0, h1), pack2h(h2, h3));
            *reinterpret_cast<uint2*>(smem + XL + off) = make_uint2(
                pack2h(__float2half_rn(v.x - __half2float(h0)),
                       __float2half_rn(v.y - __half2float(h1))),
                pack2h(__float2half_rn(v.z - __half2float(h2)),
                       __float2half_rn(v.w - __half2float(h3))));
        }
        // w[j] = r . x_j
#pragma unroll 1
        for (int jr = 0; jr < 16; jr++) {
            int j = rowBase + jr;
            float4 v = reinterpret_cast<const float4*>(xw)[j * 32 + lane];
            float p = v.x * rfrag0 + v.y * rfrag1 + v.z * rfrag2 + v.w * rfrag3;
            p += __shfl_xor_sync(0xffffffffu, p, 16);
            p += __shfl_xor_sync(0xffffffffu, p, 8);
            p += __shfl_xor_sync(0xffffffffu, p, 4);
            p += __shfl_xor_sync(0xffffffffu, p, 2);
            p += __shfl_xor_sync(0xffffffffu, p, 1);
            if (lane == 0) sw[j] = p;
        }
        __syncthreads();                 // (1) xh/xl, sw ready; prior G4 done

        // ---- GEMM1 (3-term): t = x M^T -> register fragments ----
        gemm3_sa(c2, sb + XH, sb + MH, arow, acb, brl, bcb);
        pack_split(c2, fh, fl);

        // ---- fused GEMM2+GEMM3: S and vT in one pass over x tiles ----
        gemm_g2g3(c2, c3, fh, fl, sb + XH, sb + XL, sb + WVH, arow, acb, brl, bcb);

        // softmax on c2 (+w col bias) -> P fragments
#pragma unroll
        for (int h = 0; h < 2; h++) {
            float m = -1e30f;
#pragma unroll
            for (int nt = 0; nt < 16; nt++) {
                int col = nt * 8 + cq;
                c2[nt][2 * h] += sw[col];
                c2[nt][2 * h + 1] += sw[col + 1];
                m = fmaxf(m, fmaxf(c2[nt][2 * h], c2[nt][2 * h + 1]));
            }
            m = fmaxf(m, __shfl_xor_sync(0xffffffffu, m, 1));
            m = fmaxf(m, __shfl_xor_sync(0xffffffffu, m, 2));
            float s = 0.0f;
#pragma unroll
            for (int nt = 0; nt < 16; nt++) {
                float e0 = __expf(c2[nt][2 * h] - m);
                float e1 = __expf(c2[nt][2 * h + 1] - m);
                c2[nt][2 * h] = e0;
                c2[nt][2 * h + 1] = e1;
                s += e0 + e1;
            }
            s += __shfl_xor_sync(0xffffffffu, s, 1);
            s += __shfl_xor_sync(0xffffffffu, s, 2);
            float inv = 1.0f / s;
#pragma unroll
            for (int nt = 0; nt < 16; nt++) {
                c2[nt][2 * h] *= inv;
                c2[nt][2 * h + 1] *= inv;
            }
        }
        pack_split(c2, fh, fl);          // P fragments

        // vT epilogue (c3 + bv row) -> vbuf (single fp16 image)
#pragma unroll
        for (int h = 0; h < 2; h++) {
            int row = rowBase + h * 8 + rq;
            float br = sbv[row];
#pragma unroll
            for (int nt = 0; nt < 16; nt++) {
                int col = nt * 8 + cq;
                *reinterpret_cast<uint32_t*>(smem + VTB + toff(row, col * 2)) =
                    pack2h(__float2half_rn(c3[nt][2 * h] + br),
                           __float2half_rn(c3[nt][2 * h + 1] + br));
            }
        }
        __syncthreads();                 // (2) vT visible to all warps

        // ---- GEMM4 (2-term): O = P vT^T -> out ----
        gemm2_ra(c2, fh, fl, sb + VTB, brl, bcb);
        {
            float* outw = out + (size_t)w * (WIN * 128);
#pragma unroll
            for (int h = 0; h < 2; h++) {
                int row = rowBase + h * 8 + rq;
#pragma unroll
                for (int nt = 0; nt < 16; nt++) {
                    int col = nt * 8 + cq;
                    *reinterpret_cast<float2*>(outw + row * 128 + col) =
                        make_float2(c2[nt][2 * h], c2[nt][2 * h + 1]);
                }
            }
        }
        // no trailing sync: next iteration's barrier (1) orders G4's VTB/XH
        // reads before any subsequent overwrite.
    }
}

extern "C" void kernel_launch(void* const* d_in, const int* in_sizes, int n_in,
                              void* d_out, int out_size) {
    const float* x  = (const float*)d_in[0];
    const float* Wq = (const float*)d_in[1];
    const float* bq = (const float*)d_in[2];
    const float* Wk = (const float*)d_in[3];
    const float* Wv = (const float*)d_in[5];
    const float* bv = (const float*)d_in[6];
    float* out = (float*)d_out;

    int nwin = in_sizes[0] / (WIN * 128);

    prep_all<<<128, 128>>>(Wq, bq, Wk, Wv);

    cudaFuncSetAttribute(win_attn, cudaFuncAttributeMaxDynamicSharedMemorySize, SMEM_BYTES);
    int grid = nwin < 148 ? nwin : 148;
    win_attn<<<grid, 256, SMEM_BYTES>>>(x, bv, out, nwin);
}

// round 9
// speedup vs baseline: 1.8797x; 1.1741x over previous
#include <cuda_runtime.h>
#include <cuda_fp16.h>
#include <cstdint>
#include <cstddef>

// ============================================================================
// Windowed self-attention via mma.sync.m16n8k16 fp16 (split-fp32, fp32 acc).
// S-equiv = (x M^T + r) x^T  (M = Wq^T Wk, r = bq Wk; row-consts cancel in
// softmax). 4 GEMMs/window: t = x M^T + r (3-term), S = t x^T (3-term),
// vT = Wv x^T + bv (2-term), O = P vT^T (2-term).
// G2+G3 fused (shared x B-tiles, dual accumulators). Next window's x
// load/split overlapped with G4. 8 warps x 16 rows, 256 thr, persistent CTAs.
// ============================================================================

#define WIN 128
// smem layout (bytes from 1KB-aligned base)
#define XH   0
#define XL   32768
#define MH   65536
#define WVH  131072
#define VTB  196608
#define OFF_BV 229376
#define OFF_R  229888
#define SMEM_PAYLOAD 230400
#define SMEM_BYTES (SMEM_PAYLOAD + 1024)

__device__ __forceinline__ uint32_t smem_u32(const void* p) {
    uint32_t a;
    asm("{ .reg .u64 t; cvta.to.shared.u64 t, %1; cvt.u32.u64 %0, t; }" : "=r"(a) : "l"(p));
    return a;
}

// Tile: 128 rows x 128 fp16 (256B/row, 16 chunks of 16B), XOR-swizzled.
__device__ __forceinline__ uint32_t toff(int row, int byteCol) {
    int chunk = byteCol >> 4;
    return (uint32_t)(row * 256 + (((chunk ^ (row & 7)) << 4) | (byteCol & 15)));
}

__device__ __forceinline__ uint32_t pack2h(__half a, __half b) {
    return (uint32_t)__half_as_ushort(a) | ((uint32_t)__half_as_ushort(b) << 16);
}

__device__ __forceinline__ void ldsm4(uint32_t r[4], uint32_t addr) {
    asm volatile("ldmatrix.sync.aligned.m8n8.x4.shared.b16 {%0,%1,%2,%3}, [%4];"
                 : "=r"(r[0]), "=r"(r[1]), "=r"(r[2]), "=r"(r[3]) : "r"(addr));
}

__device__ __forceinline__ void mma16816(float* c, const uint32_t a[4],
                                         uint32_t b0, uint32_t b1) {
    asm volatile(
        "mma.sync.aligned.m16n8k16.row.col.f32.f16.f16.f32 "
        "{%0,%1,%2,%3}, {%4,%5,%6,%7}, {%8,%9}, {%0,%1,%2,%3};"
        : "+f"(c[0]), "+f"(c[1]), "+f"(c[2]), "+f"(c[3])
        : "r"(a[0]), "r"(a[1]), "r"(a[2]), "r"(a[3]), "r"(b0), "r"(b1));
}

// Pre-split + pre-swizzled images: [M^T hi, M^T lo, Wv hi, Wv lo]
__device__ __align__(16) __half g_img[4 * 16384];
__device__ float g_r[128];

// ---- fused prep: M image, Wv image, r vector ----
__global__ void prep_all(const float* __restrict__ Wq, const float* __restrict__ bq,
                         const float* __restrict__ Wk, const float* __restrict__ Wv) {
    __shared__ float wkcol[128];
    __shared__ float red[4];
    int f = blockIdx.x, e = threadIdx.x;
    wkcol[e] = Wk[e * 128 + f];
    __syncthreads();
    // M[e,f] = sum_d Wq[d,e] Wk[d,f]  -> B-image row f, col e
    float acc = 0.0f;
#pragma unroll 8
    for (int d = 0; d < 128; d++)
        acc += Wq[d * 128 + e] * wkcol[d];
    uint32_t o = toff(f, e * 2) >> 1;
    {
        __half h = __float2half_rn(acc);
        g_img[o] = h;
        g_img[16384 + o] = __float2half_rn(acc - __half2float(h));
    }
    // Wv image: row f(=d), col e
    {
        float v = Wv[f * 128 + e];
        __half h = __float2half_rn(v);
        g_img[2 * 16384 + o] = h;
        g_img[3 * 16384 + o] = __float2half_rn(v - __half2float(h));
    }
    // r[f] = sum_d bq[d] Wk[d,f]
    float p = bq[e] * wkcol[e];
#pragma unroll
    for (int m = 16; m >= 1; m >>= 1) p += __shfl_xor_sync(0xffffffffu, p, m);
    if ((e & 31) == 0) red[e >> 5] = p;
    __syncthreads();
    if (e == 0) g_r[f] = red[0] + red[1] + red[2] + red[3];
}

// copy one pre-swizzled hi+lo image pair (64KB) into smem (256 threads)
__device__ __forceinline__ void copy_img64(char* dst, int pairIdx, int tid) {
    const uint4* s4 = reinterpret_cast<const uint4*>(g_img + (size_t)pairIdx * 32768);
    uint4* d4 = reinterpret_cast<uint4*>(dst);
#pragma unroll
    for (int i = 0; i < 16; i++) d4[tid + i * 256] = s4[tid + i * 256];
}

// load + split one window of x into XH/XL (all 256 threads)
__device__ __forceinline__ void load_x(const float* __restrict__ xw, char* smem, int tid) {
#pragma unroll
    for (int i = 0; i < 16; i++) {
        int idx4 = i * 256 + tid;
        int row = idx4 >> 5, col4 = idx4 & 31;
        float4 v = reinterpret_cast<const float4*>(xw)[idx4];
        __half h0 = __float2half_rn(v.x), h1 = __float2half_rn(v.y);
        __half h2 = __float2half_rn(v.z), h3 = __float2half_rn(v.w);
        uint32_t off = toff(row, col4 * 8);
        *reinterpret_cast<uint2*>(smem + XH + off) =
            make_uint2(pack2h(h0, h1), pack2h(h2, h3));
        *reinterpret_cast<uint2*>(smem + XL + off) = make_uint2(
            pack2h(__float2half_rn(v.x - __half2float(h0)),
                   __float2half_rn(v.y - __half2float(h1))),
            pack2h(__float2half_rn(v.z - __half2float(h2)),
                   __float2half_rn(v.w - __half2float(h3))));
    }
}

// ---- GEMM1 (3-term): A smem hi/lo, B smem hi/lo ----
__device__ __forceinline__ void gemm3_sa(float (&c)[16][4],
                                         uint32_t aBase, uint32_t bBase,
                                         int arow, int acb, int brl, int bcb) {
#pragma unroll
    for (int nt = 0; nt < 16; nt++)
#pragma unroll
        for (int i = 0; i < 4; i++) c[nt][i] = 0.0f;
#pragma unroll 1
    for (int kt = 0; kt < 8; kt++) {
        uint32_t ah[4], al[4];
        {
            uint32_t off = (uint32_t)(arow * 256 + (((kt * 2 + acb) ^ (arow & 7)) << 4));
            ldsm4(ah, aBase + off);
            ldsm4(al, aBase + 32768u + off);
        }
#pragma unroll
        for (int ng = 0; ng < 8; ng++) {
            int brow = ng * 16 + brl;
            uint32_t boff = (uint32_t)(brow * 256 + (((kt * 2 + bcb) ^ (brow & 7)) << 4));
            uint32_t bh[4], bl[4];
            ldsm4(bh, bBase + boff);
            ldsm4(bl, bBase + 32768u + boff);
#pragma unroll
            for (int s = 0; s < 2; s++) {
                float* cc = c[ng * 2 + s];
                mma16816(cc, ah, bh[2 * s], bh[2 * s + 1]);
                mma16816(cc, ah, bl[2 * s], bl[2 * s + 1]);
                mma16816(cc, al, bh[2 * s], bh[2 * s + 1]);
            }
        }
    }
}

// ---- fused G2+G3: shared B tiles (x), two accumulation streams ----
// c2: S = t x^T (3-term, A = t register fragments)
// c3: vT = Wv x^T (2-term, A = Wv smem hi/lo)
__device__ __forceinline__ void gemm_g2g3(float (&c2)[16][4], float (&c3)[16][4],
                                          const uint32_t (&th)[16][2],
                                          const uint32_t (&tl)[16][2],
                                          uint32_t xh, uint32_t xl, uint32_t wv,
                                          int arow, int acb, int brl, int bcb) {
#pragma unroll
    for (int nt = 0; nt < 16; nt++)
#pragma unroll
        for (int i = 0; i < 4; i++) { c2[nt][i] = 0.0f; c3[nt][i] = 0.0f; }
#pragma unroll
    for (int kt = 0; kt < 8; kt++) {
        uint32_t ah3[4], al3[4];
        {
            uint32_t aoff = (uint32_t)(arow * 256 + (((kt * 2 + acb) ^ (arow & 7)) << 4));
            ldsm4(ah3, wv + aoff);
            ldsm4(al3, wv + 32768u + aoff);
        }
        uint32_t ah2[4] = {th[2 * kt][0], th[2 * kt][1], th[2 * kt + 1][0], th[2 * kt + 1][1]};
        uint32_t al2[4] = {tl[2 * kt][0], tl[2 * kt][1], tl[2 * kt + 1][0], tl[2 * kt + 1][1]};
#pragma unroll
        for (int ng = 0; ng < 8; ng++) {
            int brow = ng * 16 + brl;
            uint32_t boff = (uint32_t)(brow * 256 + (((kt * 2 + bcb) ^ (brow & 7)) << 4));
            uint32_t bh[4], bl[4];
            ldsm4(bh, xh + boff);
            ldsm4(bl, xl + boff);
#pragma unroll
            for (int s = 0; s < 2; s++) {
                float* cS = c2[ng * 2 + s];
                float* cV = c3[ng * 2 + s];
                mma16816(cS, ah2, bh[2 * s], bh[2 * s + 1]);
                mma16816(cV, ah3, bh[2 * s], bh[2 * s + 1]);
                mma16816(cS, ah2, bl[2 * s], bl[2 * s + 1]);
                mma16816(cV, al3, bh[2 * s], bh[2 * s + 1]);
                mma16816(cS, al2, bh[2 * s], bh[2 * s + 1]);
            }
        }
    }
}

// ---- GEMM4 (2-term): A register fragments, B single image ----
__device__ __forceinline__ void gemm2_ra(float (&c)[16][4],
                                         const uint32_t (&th)[16][2],
                                         const uint32_t (&tl)[16][2],
                                         uint32_t bBase, int brl, int bcb) {
#pragma unroll
    for (int nt = 0; nt < 16; nt++)
#pragma unroll
        for (int i = 0; i < 4; i++) c[nt][i] = 0.0f;
#pragma unroll
    for (int kt = 0; kt < 8; kt++) {
        uint32_t ah[4] = {th[2 * kt][0], th[2 * kt][1], th[2 * kt + 1][0], th[2 * kt + 1][1]};
        uint32_t al[4] = {tl[2 * kt][0], tl[2 * kt][1], tl[2 * kt + 1][0], tl[2 * kt + 1][1]};
#pragma unroll
        for (int ng = 0; ng < 8; ng++) {
            int brow = ng * 16 + brl;
            uint32_t boff = (uint32_t)(brow * 256 + (((kt * 2 + bcb) ^ (brow & 7)) << 4));
            uint32_t bh[4];
            ldsm4(bh, bBase + boff);
#pragma unroll
            for (int s = 0; s < 2; s++) {
                float* cc = c[ng * 2 + s];
                mma16816(cc, ah, bh[2 * s], bh[2 * s + 1]);
                mma16816(cc, al, bh[2 * s], bh[2 * s + 1]);
            }
        }
    }
}

// pack C fragments into hi/lo fp16 A-fragments for the next GEMM
__device__ __forceinline__ void pack_split(const float (&c)[16][4],
                                           uint32_t (&h)[16][2], uint32_t (&l)[16][2]) {
#pragma unroll
    for (int nt = 0; nt < 16; nt++)
#pragma unroll
        for (int j = 0; j < 2; j++) {
            float v0 = c[nt][2 * j], v1 = c[nt][2 * j + 1];
            __half h0 = __float2half_rn(v0), h1 = __float2half_rn(v1);
            h[nt][j] = pack2h(h0, h1);
            l[nt][j] = pack2h(__float2half_rn(v0 - __half2float(h0)),
                              __float2half_rn(v1 - __half2float(h1)));
        }
}

// same, but add per-column bias r first (t epilogue: t += r)
__device__ __forceinline__ void pack_split_bias(const float (&c)[16][4],
                                                uint32_t (&h)[16][2], uint32_t (&l)[16][2],
                                                const float* sr, int cq) {
#pragma unroll
    for (int nt = 0; nt < 16; nt++) {
        float rA = sr[nt * 8 + cq], rB = sr[nt * 8 + cq + 1];
#pragma unroll
        for (int j = 0; j < 2; j++) {
            float v0 = c[nt][2 * j] + rA, v1 = c[nt][2 * j + 1] + rB;
            __half h0 = __float2half_rn(v0), h1 = __float2half_rn(v1);
            h[nt][j] = pack2h(h0, h1);
            l[nt][j] = pack2h(__float2half_rn(v0 - __half2float(h0)),
                              __float2half_rn(v1 - __half2float(h1)));
        }
    }
}

__global__ void __launch_bounds__(256, 1)
win_attn(const float* __restrict__ x, const float* __restrict__ bv,
         float* __restrict__ out, int nwin) {
    extern __shared__ char smem_raw[];
    uint32_t sraw = smem_u32(smem_raw);
    uint32_t sb = (sraw + 1023u) & ~1023u;
    char* smem = smem_raw + (sb - sraw);

    const int tid = threadIdx.x, wid = tid >> 5, lane = tid & 31;

    float* sbv = reinterpret_cast<float*>(smem + OFF_BV);
    float* sr  = reinterpret_cast<float*>(smem + OFF_R);
    if (tid < 128) {
        sbv[tid] = bv[tid];
        sr[tid] = g_r[tid];
    }
    // resident weight images
    copy_img64(smem + MH, 0, tid);
    copy_img64(smem + WVH, 1, tid);

    // ldmatrix lane mappings
    const int arl = (lane & 7) + ((lane >> 3) & 1) * 8, acb = (lane >> 4) & 1;
    const int brl = (lane & 7) + ((lane >> 4) & 1) * 8, bcb = (lane >> 3) & 1;
    const int rq = lane >> 2, cq = 2 * (lane & 3);
    const int rowBase = wid * 16;
    const int arow = rowBase + arl;

    float c2[16][4], c3[16][4];
    uint32_t fh[16][2], fl[16][2];   // A-fragments: t, then P

    int w = blockIdx.x;
    if (w < nwin) load_x(x + (size_t)w * (WIN * 128), smem, tid);
    __syncthreads();                     // x(w0), images, biases ready

    while (w < nwin) {
        // ---- GEMM1 (3-term): t = x M^T ; t += r ; -> register fragments ----
        gemm3_sa(c2, sb + XH, sb + MH, arow, acb, brl, bcb);
        pack_split_bias(c2, fh, fl, sr, cq);

        // ---- fused GEMM2+GEMM3: S and vT in one pass over x tiles ----
        gemm_g2g3(c2, c3, fh, fl, sb + XH, sb + XL, sb + WVH, arow, acb, brl, bcb);

        // softmax on c2 -> P fragments
#pragma unroll
        for (int h = 0; h < 2; h++) {
            float m = -1e30f;
#pragma unroll
            for (int nt = 0; nt < 16; nt++)
                m = fmaxf(m, fmaxf(c2[nt][2 * h], c2[nt][2 * h + 1]));
            m = fmaxf(m, __shfl_xor_sync(0xffffffffu, m, 1));
            m = fmaxf(m, __shfl_xor_sync(0xffffffffu, m, 2));
            float s = 0.0f;
#pragma unroll
            for (int nt = 0; nt < 16; nt++) {
                float e0 = __expf(c2[nt][2 * h] - m);
                float e1 = __expf(c2[nt][2 * h + 1] - m);
                c2[nt][2 * h] = e0;
                c2[nt][2 * h + 1] = e1;
                s += e0 + e1;
            }
            s += __shfl_xor_sync(0xffffffffu, s, 1);
            s += __shfl_xor_sync(0xffffffffu, s, 2);
            float inv = 1.0f / s;
#pragma unroll
            for (int nt = 0; nt < 16; nt++) {
                c2[nt][2 * h] *= inv;
                c2[nt][2 * h + 1] *= inv;
            }
        }
        pack_split(c2, fh, fl);          // P fragments

        // vT epilogue (c3 + bv row) -> vbuf (single fp16 image)
#pragma unroll
        for (int h = 0; h < 2; h++) {
            int row = rowBase + h * 8 + rq;
            float br = sbv[row];
#pragma unroll
            for (int nt = 0; nt < 16; nt++) {
                int col = nt * 8 + cq;
                *reinterpret_cast<uint32_t*>(smem + VTB + toff(row, col * 2)) =
                    pack2h(__float2half_rn(c3[nt][2 * h] + br),
                           __float2half_rn(c3[nt][2 * h + 1] + br));
            }
        }
        __syncthreads();                 // (2) vT visible; XH/XL dead everywhere

        // ---- overlap: load x for next window while G4 runs ----
        int wn = w + gridDim.x;
        if (wn < nwin) load_x(x + (size_t)wn * (WIN * 128), smem, tid);

        // ---- GEMM4 (2-term): O = P vT^T -> out ----
        gemm2_ra(c2, fh, fl, sb + VTB, brl, bcb);
        {
            float* outw = out + (size_t)w * (WIN * 128);
#pragma unroll
            for (int h = 0; h < 2; h++) {
                int row = rowBase + h * 8 + rq;
#pragma unroll
                for (int nt = 0; nt < 16; nt++) {
                    int col = nt * 8 + cq;
                    *reinterpret_cast<float2*>(outw + row * 128 + col) =
                        make_float2(c2[nt][2 * h], c2[nt][2 * h + 1]);
                }
            }
        }
        __syncthreads();                 // (1) new x ready; VTB dead

        w = wn;
    }
}

extern "C" void kernel_launch(void* const* d_in, const int* in_sizes, int n_in,
                              void* d_out, int out_size) {
    const float* x  = (const float*)d_in[0];
    const float* Wq = (const float*)d_in[1];
    const float* bq = (const float*)d_in[2];
    const float* Wk = (const float*)d_in[3];
    const float* Wv = (const float*)d_in[5];
    const float* bv = (const float*)d_in[6];
    float* out = (float*)d_out;

    int nwin = in_sizes[0] / (WIN * 128);

    prep_all<<<128, 128>>>(Wq, bq, Wk, Wv);

    cudaFuncSetAttribute(win_attn, cudaFuncAttributeMaxDynamicSharedMemorySize, SMEM_BYTES);
    int grid = nwin < 148 ? nwin : 148;
    win_attn<<<grid, 256, SMEM_BYTES>>>(x, bv, out, nwin);
}

// round 10
// speedup vs baseline: 2.1551x; 1.1465x over previous
#include <cuda_runtime.h>
#include <cuda_fp16.h>
#include <cstdint>
#include <cstddef>

// ============================================================================
// Windowed self-attention via mma.sync.m16n8k16 fp16 (split-fp32, fp32 acc).
// S-equiv = (x M^T + r) x^T  (M = Wq^T Wk, r = bq Wk; row-consts cancel in
// softmax). 4 GEMMs/window: t = x M^T + r (3-term), S = t x^T (3-term),
// vT = Wvh xh^T + bv (1-term), O = Ph vT^T (1-term).
// G2+G3 fused (shared x B-tiles, dual accumulators). Next window's x
// load/split overlapped with G4. 8 warps x 16 rows, 256 thr, persistent CTAs.
// ============================================================================

#define WIN 128
// smem layout (bytes from 1KB-aligned base)
#define XH   0
#define XL   32768
#define MH   65536
#define WVH  131072
#define VTB  163840
#define OFF_BV 196608
#define OFF_R  197120
#define SMEM_PAYLOAD 197632
#define SMEM_BYTES (SMEM_PAYLOAD + 1024)

__device__ __forceinline__ uint32_t smem_u32(const void* p) {
    uint32_t a;
    asm("{ .reg .u64 t; cvta.to.shared.u64 t, %1; cvt.u32.u64 %0, t; }" : "=r"(a) : "l"(p));
    return a;
}

// Tile: 128 rows x 128 fp16 (256B/row, 16 chunks of 16B), XOR-swizzled.
__device__ __forceinline__ uint32_t toff(int row, int byteCol) {
    int chunk = byteCol >> 4;
    return (uint32_t)(row * 256 + (((chunk ^ (row & 7)) << 4) | (byteCol & 15)));
}

__device__ __forceinline__ uint32_t pack2h(__half a, __half b) {
    return (uint32_t)__half_as_ushort(a) | ((uint32_t)__half_as_ushort(b) << 16);
}

__device__ __forceinline__ void ldsm4(uint32_t r[4], uint32_t addr) {
    asm volatile("ldmatrix.sync.aligned.m8n8.x4.shared.b16 {%0,%1,%2,%3}, [%4];"
                 : "=r"(r[0]), "=r"(r[1]), "=r"(r[2]), "=r"(r[3]) : "r"(addr));
}

__device__ __forceinline__ void mma16816(float* c, const uint32_t a[4],
                                         uint32_t b0, uint32_t b1) {
    asm volatile(
        "mma.sync.aligned.m16n8k16.row.col.f32.f16.f16.f32 "
        "{%0,%1,%2,%3}, {%4,%5,%6,%7}, {%8,%9}, {%0,%1,%2,%3};"
        : "+f"(c[0]), "+f"(c[1]), "+f"(c[2]), "+f"(c[3])
        : "r"(a[0]), "r"(a[1]), "r"(a[2]), "r"(a[3]), "r"(b0), "r"(b1));
}

// Pre-split + pre-swizzled images: [M^T hi, M^T lo, Wv hi]
__device__ __align__(16) __half g_img[3 * 16384];
__device__ float g_r[128];

// ---- fused prep: M image, Wv image, r vector ----
__global__ void prep_all(const float* __restrict__ Wq, const float* __restrict__ bq,
                         const float* __restrict__ Wk, const float* __restrict__ Wv) {
    __shared__ float wkcol[128];
    __shared__ float red[4];
    int f = blockIdx.x, e = threadIdx.x;
    wkcol[e] = Wk[e * 128 + f];
    __syncthreads();
    // M[e,f] = sum_d Wq[d,e] Wk[d,f]  -> B-image row f, col e
    float acc = 0.0f;
#pragma unroll 8
    for (int d = 0; d < 128; d++)
        acc += Wq[d * 128 + e] * wkcol[d];
    uint32_t o = toff(f, e * 2) >> 1;
    {
        __half h = __float2half_rn(acc);
        g_img[o] = h;
        g_img[16384 + o] = __float2half_rn(acc - __half2float(h));
    }
    // Wv hi image: row f(=d), col e
    g_img[2 * 16384 + o] = __float2half_rn(Wv[f * 128 + e]);
    // r[f] = sum_d bq[d] Wk[d,f]
    float p = bq[e] * wkcol[e];
#pragma unroll
    for (int m = 16; m >= 1; m >>= 1) p += __shfl_xor_sync(0xffffffffu, p, m);
    if ((e & 31) == 0) red[e >> 5] = p;
    __syncthreads();
    if (e == 0) g_r[f] = red[0] + red[1] + red[2] + red[3];
}

// copy pre-swizzled 32KB images into smem (256 threads)
__device__ __forceinline__ void copy_img32(char* dst, int imgIdx, int tid) {
    const uint4* s4 = reinterpret_cast<const uint4*>(g_img + (size_t)imgIdx * 16384);
    uint4* d4 = reinterpret_cast<uint4*>(dst);
#pragma unroll
    for (int i = 0; i < 8; i++) d4[tid + i * 256] = s4[tid + i * 256];
}

// load + split one window of x into XH/XL (all 256 threads)
__device__ __forceinline__ void load_x(const float* __restrict__ xw, char* smem, int tid) {
#pragma unroll
    for (int i = 0; i < 16; i++) {
        int idx4 = i * 256 + tid;
        int row = idx4 >> 5, col4 = idx4 & 31;
        float4 v = reinterpret_cast<const float4*>(xw)[idx4];
        __half h0 = __float2half_rn(v.x), h1 = __float2half_rn(v.y);
        __half h2 = __float2half_rn(v.z), h3 = __float2half_rn(v.w);
        uint32_t off = toff(row, col4 * 8);
        *reinterpret_cast<uint2*>(smem + XH + off) =
            make_uint2(pack2h(h0, h1), pack2h(h2, h3));
        *reinterpret_cast<uint2*>(smem + XL + off) = make_uint2(
            pack2h(__float2half_rn(v.x - __half2float(h0)),
                   __float2half_rn(v.y - __half2float(h1))),
            pack2h(__float2half_rn(v.z - __half2float(h2)),
                   __float2half_rn(v.w - __half2float(h3))));
    }
}

// ---- GEMM1 (3-term): A smem hi/lo, B smem hi/lo ----
__device__ __forceinline__ void gemm3_sa(float (&c)[16][4],
                                         uint32_t aBase, uint32_t bBase,
                                         int arow, int acb, int brl, int bcb) {
#pragma unroll
    for (int nt = 0; nt < 16; nt++)
#pragma unroll
        for (int i = 0; i < 4; i++) c[nt][i] = 0.0f;
#pragma unroll 1
    for (int kt = 0; kt < 8; kt++) {
        uint32_t ah[4], al[4];
        {
            uint32_t off = (uint32_t)(arow * 256 + (((kt * 2 + acb) ^ (arow & 7)) << 4));
            ldsm4(ah, aBase + off);
            ldsm4(al, aBase + 32768u + off);
        }
#pragma unroll
        for (int ng = 0; ng < 8; ng++) {
            int brow = ng * 16 + brl;
            uint32_t boff = (uint32_t)(brow * 256 + (((kt * 2 + bcb) ^ (brow & 7)) << 4));
            uint32_t bh[4], bl[4];
            ldsm4(bh, bBase + boff);
            ldsm4(bl, bBase + 32768u + boff);
#pragma unroll
            for (int s = 0; s < 2; s++) {
                float* cc = c[ng * 2 + s];
                mma16816(cc, ah, bh[2 * s], bh[2 * s + 1]);
                mma16816(cc, ah, bl[2 * s], bl[2 * s + 1]);
                mma16816(cc, al, bh[2 * s], bh[2 * s + 1]);
            }
        }
    }
}

// ---- fused G2+G3: shared B tiles (x), two accumulation streams ----
// c2: S = t x^T (3-term, A = t register fragments)
// c3: vT = Wvh xh^T (1-term, A = Wv hi smem)
__device__ __forceinline__ void gemm_g2g3(float (&c2)[16][4], float (&c3)[16][4],
                                          const uint32_t (&th)[16][2],
                                          const uint32_t (&tl)[16][2],
                                          uint32_t xh, uint32_t xl, uint32_t wv,
                                          int arow, int acb, int brl, int bcb) {
#pragma unroll
    for (int nt = 0; nt < 16; nt++)
#pragma unroll
        for (int i = 0; i < 4; i++) { c2[nt][i] = 0.0f; c3[nt][i] = 0.0f; }
#pragma unroll
    for (int kt = 0; kt < 8; kt++) {
        uint32_t ah3[4];
        {
            uint32_t aoff = (uint32_t)(arow * 256 + (((kt * 2 + acb) ^ (arow & 7)) << 4));
            ldsm4(ah3, wv + aoff);
        }
        uint32_t ah2[4] = {th[2 * kt][0], th[2 * kt][1], th[2 * kt + 1][0], th[2 * kt + 1][1]};
        uint32_t al2[4] = {tl[2 * kt][0], tl[2 * kt][1], tl[2 * kt + 1][0], tl[2 * kt + 1][1]};
#pragma unroll
        for (int ng = 0; ng < 8; ng++) {
            int brow = ng * 16 + brl;
            uint32_t boff = (uint32_t)(brow * 256 + (((kt * 2 + bcb) ^ (brow & 7)) << 4));
            uint32_t bh[4], bl[4];
            ldsm4(bh, xh + boff);
            ldsm4(bl, xl + boff);
#pragma unroll
            for (int s = 0; s < 2; s++) {
                float* cS = c2[ng * 2 + s];
                float* cV = c3[ng * 2 + s];
                mma16816(cS, ah2, bh[2 * s], bh[2 * s + 1]);
                mma16816(cV, ah3, bh[2 * s], bh[2 * s + 1]);
                mma16816(cS, ah2, bl[2 * s], bl[2 * s + 1]);
                mma16816(cS, al2, bh[2 * s], bh[2 * s + 1]);
            }
        }
    }
}

// ---- GEMM4 (1-term): A register fragments (hi only), B single image ----
__device__ __forceinline__ void gemm1_ra(float (&c)[16][4],
                                         const uint32_t (&th)[16][2],
                                         uint32_t bBase, int brl, int bcb) {
#pragma unroll
    for (int nt = 0; nt < 16; nt++)
#pragma unroll
        for (int i = 0; i < 4; i++) c[nt][i] = 0.0f;
#pragma unroll
    for (int kt = 0; kt < 8; kt++) {
        uint32_t ah[4] = {th[2 * kt][0], th[2 * kt][1], th[2 * kt + 1][0], th[2 * kt + 1][1]};
#pragma unroll
        for (int ng = 0; ng < 8; ng++) {
            int brow = ng * 16 + brl;
            uint32_t boff = (uint32_t)(brow * 256 + (((kt * 2 + bcb) ^ (brow & 7)) << 4));
            uint32_t bh[4];
            ldsm4(bh, bBase + boff);
#pragma unroll
            for (int s = 0; s < 2; s++) {
                float* cc = c[ng * 2 + s];
                mma16816(cc, ah, bh[2 * s], bh[2 * s + 1]);
            }
        }
    }
}

// pack C fragments into hi-only fp16 A-fragments (for P)
__device__ __forceinline__ void pack_hi(const float (&c)[16][4], uint32_t (&h)[16][2]) {
#pragma unroll
    for (int nt = 0; nt < 16; nt++)
#pragma unroll
        for (int j = 0; j < 2; j++)
            h[nt][j] = pack2h(__float2half_rn(c[nt][2 * j]),
                              __float2half_rn(c[nt][2 * j + 1]));
}

// pack C fragments into hi/lo fp16 A-fragments, adding per-column bias r (t)
__device__ __forceinline__ void pack_split_bias(const float (&c)[16][4],
                                                uint32_t (&h)[16][2], uint32_t (&l)[16][2],
                                                const float* sr, int cq) {
#pragma unroll
    for (int nt = 0; nt < 16; nt++) {
        float rA = sr[nt * 8 + cq], rB = sr[nt * 8 + cq + 1];
#pragma unroll
        for (int j = 0; j < 2; j++) {
            float v0 = c[nt][2 * j] + rA, v1 = c[nt][2 * j + 1] + rB;
            __half h0 = __float2half_rn(v0), h1 = __float2half_rn(v1);
            h[nt][j] = pack2h(h0, h1);
            l[nt][j] = pack2h(__float2half_rn(v0 - __half2float(h0)),
                              __float2half_rn(v1 - __half2float(h1)));
        }
    }
}

__global__ void __launch_bounds__(256, 1)
win_attn(const float* __restrict__ x, const float* __restrict__ bv,
         float* __restrict__ out, int nwin) {
    extern __shared__ char smem_raw[];
    uint32_t sraw = smem_u32(smem_raw);
    uint32_t sb = (sraw + 1023u) & ~1023u;
    char* smem = smem_raw + (sb - sraw);

    const int tid = threadIdx.x, wid = tid >> 5, lane = tid & 31;

    float* sbv = reinterpret_cast<float*>(smem + OFF_BV);
    float* sr  = reinterpret_cast<float*>(smem + OFF_R);
    if (tid < 128) {
        sbv[tid] = bv[tid];
        sr[tid] = g_r[tid];
    }
    // resident weight images: M hi, M lo, Wv hi
    copy_img32(smem + MH, 0, tid);
    copy_img32(smem + MH + 32768, 1, tid);
    copy_img32(smem + WVH, 2, tid);

    // ldmatrix lane mappings
    const int arl = (lane & 7) + ((lane >> 3) & 1) * 8, acb = (lane >> 4) & 1;
    const int brl = (lane & 7) + ((lane >> 4) & 1) * 8, bcb = (lane >> 3) & 1;
    const int rq = lane >> 2, cq = 2 * (lane & 3);
    const int rowBase = wid * 16;
    const int arow = rowBase + arl;

    float c2[16][4], c3[16][4];
    uint32_t fh[16][2], fl[16][2];   // A-fragments: t (hi/lo), then P (hi)

    int w = blockIdx.x;
    if (w < nwin) load_x(x + (size_t)w * (WIN * 128), smem, tid);
    __syncthreads();                     // x(w0), images, biases ready

    while (w < nwin) {
        // ---- GEMM1 (3-term): t = x M^T ; t += r ; -> register fragments ----
        gemm3_sa(c2, sb + XH, sb + MH, arow, acb, brl, bcb);
        pack_split_bias(c2, fh, fl, sr, cq);

        // ---- fused GEMM2+GEMM3: S (3-term) and vT (1-term) over x tiles ----
        gemm_g2g3(c2, c3, fh, fl, sb + XH, sb + XL, sb + WVH, arow, acb, brl, bcb);

        // softmax on c2 -> P fragments (hi only)
#pragma unroll
        for (int h = 0; h < 2; h++) {
            float m = -1e30f;
#pragma unroll
            for (int nt = 0; nt < 16; nt++)
                m = fmaxf(m, fmaxf(c2[nt][2 * h], c2[nt][2 * h + 1]));
            m = fmaxf(m, __shfl_xor_sync(0xffffffffu, m, 1));
            m = fmaxf(m, __shfl_xor_sync(0xffffffffu, m, 2));
            float s = 0.0f;
#pragma unroll
            for (int nt = 0; nt < 16; nt++) {
                float e0 = __expf(c2[nt][2 * h] - m);
                float e1 = __expf(c2[nt][2 * h + 1] - m);
                c2[nt][2 * h] = e0;
                c2[nt][2 * h + 1] = e1;
                s += e0 + e1;
            }
            s += __shfl_xor_sync(0xffffffffu, s, 1);
            s += __shfl_xor_sync(0xffffffffu, s, 2);
            float inv = 1.0f / s;
#pragma unroll
            for (int nt = 0; nt < 16; nt++) {
                c2[nt][2 * h] *= inv;
                c2[nt][2 * h + 1] *= inv;
            }
        }
        pack_hi(c2, fh);                 // P fragments (hi only)

        // vT epilogue (c3 + bv row) -> vbuf (single fp16 image)
#pragma unroll
        for (int h = 0; h < 2; h++) {
            int row = rowBase + h * 8 + rq;
            float br = sbv[row];
#pragma unroll
            for (int nt = 0; nt < 16; nt++) {
                int col = nt * 8 + cq;
                *reinterpret_cast<uint32_t*>(smem + VTB + toff(row, col * 2)) =
                    pack2h(__float2half_rn(c3[nt][2 * h] + br),
                           __float2half_rn(c3[nt][2 * h + 1] + br));
            }
        }
        __syncthreads();                 // (2) vT visible; XH/XL dead everywhere

        // ---- overlap: load x for next window while G4 runs ----
        int wn = w + gridDim.x;
        if (wn < nwin) load_x(x + (size_t)wn * (WIN * 128), smem, tid);

        // ---- GEMM4 (1-term): O = Ph vT^T -> out ----
        gemm1_ra(c2, fh, sb + VTB, brl, bcb);
        {
            float* outw = out + (size_t)w * (WIN * 128);
#pragma unroll
            for (int h = 0; h < 2; h++) {
                int row = rowBase + h * 8 + rq;
#pragma unroll
                for (int nt = 0; nt < 16; nt++) {
                    int col = nt * 8 + cq;
                    *reinterpret_cast<float2*>(outw + row * 128 + col) =
                        make_float2(c2[nt][2 * h], c2[nt][2 * h + 1]);
                }
            }
        }
        __syncthreads();                 // (1) new x ready; VTB dead

        w = wn;
    }
}

extern "C" void kernel_launch(void* const* d_in, const int* in_sizes, int n_in,
                              void* d_out, int out_size) {
    const float* x  = (const float*)d_in[0];
    const float* Wq = (const float*)d_in[1];
    const float* bq = (const float*)d_in[2];
    const float* Wk = (const float*)d_in[3];
    const float* Wv = (const float*)d_in[5];
    const float* bv = (const float*)d_in[6];
    float* out = (float*)d_out;

    int nwin = in_sizes[0] / (WIN * 128);

    prep_all<<<128, 128>>>(Wq, bq, Wk, Wv);

    cudaFuncSetAttribute(win_attn, cudaFuncAttributeMaxDynamicSharedMemorySize, SMEM_BYTES);
    int grid = nwin < 148 ? nwin : 148;
    win_attn<<<grid, 256, SMEM_BYTES>>>(x, bv, out, nwin);
}